// round 13
// baseline (speedup 1.0000x reference)
#include <cuda_runtime.h>
#include <cuda_fp16.h>
#include <cstdint>
#include <cstddef>

#define NN 50000
#define NE 400000
#define HH 128
#define H2 256
#define BN_EPS 1e-5f

// ---------------- scratch ----------------
static __device__ float g_S [(size_t)NN * HH];
static __device__ float g_Hb[(size_t)NE * 512];
static __device__ float g_Y [(size_t)NE * HH];
static __device__ float g_Y2[(size_t)NE * HH];
static __device__ float g_stats[8][2][256];
static __device__ __half g_AH[(size_t)NE * H2];
static __device__ __half g_Wf[294912];

#define OFF_E0W1 0
#define OFF_E0W2 65536
#define OFF_E1W1 98304
#define OFF_E2W1 131072
#define OFF_E1W2 163840
#define OFF_E2W2 196608
#define OFF_NW1  229376
#define OFF_NW2  262144

static inline long cdivl(long a, long b) { return (a + b - 1) / b; }

__device__ __forceinline__ uint32_t smem_to_u32(const void* p) {
    uint32_t a;
    asm("{ .reg .u64 t; cvta.to.shared.u64 t, %1; cvt.u32.u64 %0, t; }" : "=r"(a) : "l"(p));
    return a;
}

#define LDMX4(r, addr) \
    asm volatile("ldmatrix.sync.aligned.m8n8.x4.shared.b16 {%0,%1,%2,%3}, [%4];" \
        : "=r"((r)[0]), "=r"((r)[1]), "=r"((r)[2]), "=r"((r)[3]) : "r"(addr))

#define MMA16816(d, a, b0, b1) \
    asm volatile("mma.sync.aligned.m16n8k16.row.col.f32.f16.f16.f32 " \
        "{%0,%1,%2,%3},{%4,%5,%6,%7},{%8,%9},{%0,%1,%2,%3};" \
        : "+f"((d)[0]), "+f"((d)[1]), "+f"((d)[2]), "+f"((d)[3]) \
        : "r"((a)[0]), "r"((a)[1]), "r"((a)[2]), "r"((a)[3]), "r"(b0), "r"(b1))

__device__ __forceinline__ void cp16(uint32_t dst, const void* src) {
    asm volatile("cp.async.cg.shared.global [%0], [%1], 16;" :: "r"(dst), "l"(src));
}
#define CP_COMMIT() asm volatile("cp.async.commit_group;" ::: "memory")
#define CP_WAIT(n)  asm volatile("cp.async.wait_group %0;" :: "n"(n) : "memory")

__device__ __forceinline__ void red4(float* p, float a, float b, float c, float d) {
    asm volatile("red.global.add.v4.f32 [%0], {%1,%2,%3,%4};"
                 :: "l"(p), "f"(a), "f"(b), "f"(c), "f"(d) : "memory");
}

__device__ __forceinline__ uint32_t sw64(uint32_t off) {
    return off ^ ((off >> 3) & 0x30);
}

__device__ __forceinline__ void store_h4(__half* dst, size_t idx, float4 v) {
    __half2 xy = __floats2half2_rn(v.x, v.y);
    __half2 zw = __floats2half2_rn(v.z, v.w);
    *reinterpret_cast<uint2*>(dst + idx) =
        make_uint2(*reinterpret_cast<uint32_t*>(&xy), *reinterpret_cast<uint32_t*>(&zw));
}

// ---------------- init ----------------
#define NS4 ((NN * HH) / 4)
#define R_STATS 1024
#define R_W 294912
#define INIT_TOTAL (NS4 + R_STATS + R_W)

__global__ void init_all(const float* w0, const float* w1, const float* w2, const float* w3,
                         const float* w4, const float* w5, const float* w6, const float* w7) {
    int gid = blockIdx.x * blockDim.x + threadIdx.x;
    if (gid < NS4) {
        reinterpret_cast<float4*>(g_S)[gid] = make_float4(0.f, 0.f, 0.f, 0.f);
        return;
    }
    gid -= NS4;
    if (gid < R_STATS) {
        reinterpret_cast<float4*>(g_stats)[gid] = make_float4(0.f, 0.f, 0.f, 0.f);
        return;
    }
    gid -= R_STATS;
    if (gid >= R_W) return;
    const float* ws[8] = {w0, w1, w2, w3, w4, w5, w6, w7};
    const int segSize[8] = {65536, 32768, 32768, 32768, 32768, 32768, 32768, 32768};
    const int segK[8]    = {256, 256, 128, 128, 256, 256, 128, 256};
    int seg = 0, base = 0, idx = gid;
#pragma unroll
    for (int s = 0; s < 8; s++) {
        if (idx < segSize[s]) { seg = s; break; }
        idx -= segSize[s];
        base += segSize[s];
    }
    int Kw = segK[seg];
    int Nw = segSize[seg] / Kw;
    int k = idx / Nw, n = idx % Nw;
    g_Wf[base + n * Kw + k] = __float2half_rn(ws[seg][idx]);
}

// ---------------- graph kernels ----------------
__global__ void zero_f4(float4* p, int n4) {
    int i = blockIdx.x * blockDim.x + threadIdx.x;
    if (i < n4) p[i] = make_float4(0.f, 0.f, 0.f, 0.f);
}

__global__ void scatter_edge(const float* __restrict__ edge_rep,
                             const int* __restrict__ src, const int* __restrict__ dst,
                             float* __restrict__ S) {
    int tid = blockIdx.x * blockDim.x + threadIdx.x;
    if (tid >= NE * 32) return;
    int e = tid >> 5, q = tid & 31;
    float4 v = reinterpret_cast<const float4*>(edge_rep)[(size_t)e * 32 + q];
    int s = src[e], d = dst[e];
    red4(S + (size_t)s * HH + q * 4, v.x, v.y, v.z, v.w);
    red4(S + (size_t)d * HH + q * 4, v.x, v.y, v.z, v.w);
}

__global__ void build_x0(const float* __restrict__ node_rep, const float* __restrict__ S,
                         const int* __restrict__ src, const int* __restrict__ dst,
                         __half* __restrict__ Ah) {
    int tid = blockIdx.x * blockDim.x + threadIdx.x;
    if (tid >= NE * 32) return;
    int e = tid >> 5, q = tid & 31;
    int s = src[e], d = dst[e];
    const float4* nr4 = reinterpret_cast<const float4*>(node_rep);
    const float4* S4  = reinterpret_cast<const float4*>(S);
    float4 a0 = nr4[(size_t)s * 32 + q], a1 = nr4[(size_t)d * 32 + q];
    float4 b0 = S4 [(size_t)s * 32 + q], b1 = S4 [(size_t)d * 32 + q];
    store_h4(Ah, (size_t)e * 256 + q * 4,
             make_float4(a0.x + a1.x, a0.y + a1.y, a0.z + a1.z, a0.w + a1.w));
    store_h4(Ah, (size_t)e * 256 + 128 + q * 4,
             make_float4(b0.x + b1.x, b0.y + b1.y, b0.z + b1.z, b0.w + b1.w));
}

// ---------------- MMA cores: 4 warps, warp tile 64x64 ----------------
#define S16_A 0
#define S16_B 8192
#define STG16 16384
#define GSMEM16 (3 * STG16)
#define AHIo 0
#define ALOo 8192
#define Bo   16384
#define STG32 24576
#define GSMEM32 (2 * STG32)

#define MMA_CHUNK1(uStage, acc, rAoff, rBoff, kb)                                  \
    do {                                                                           \
        uint32_t ah[4][4], bb[4][4];                                               \
        _Pragma("unroll")                                                          \
        for (int mt = 0; mt < 4; mt++) {                                           \
            uint32_t sw = sw64(rAoff[mt] + (kb));                                  \
            LDMX4(ah[mt], (uStage) + S16_A + sw);                                  \
        }                                                                          \
        _Pragma("unroll")                                                          \
        for (int t = 0; t < 4; t++) {                                              \
            uint32_t sw = sw64(rBoff[t] + (kb));                                   \
            LDMX4(bb[t], (uStage) + S16_B + sw);                                   \
        }                                                                          \
        _Pragma("unroll")                                                          \
        for (int mt = 0; mt < 4; mt++)                                             \
            _Pragma("unroll")                                                      \
            for (int t = 0; t < 4; t++) {                                          \
                MMA16816(acc[mt][t * 2 + 0], ah[mt], bb[t][0], bb[t][2]);          \
                MMA16816(acc[mt][t * 2 + 1], ah[mt], bb[t][1], bb[t][3]);          \
            }                                                                      \
    } while (0)

#define MMA_CHUNK2(uStage, acc, rAoff, rBoff, kb)                                  \
    do {                                                                           \
        uint32_t ah[4][4], al[4][4], bb[4][4];                                     \
        _Pragma("unroll")                                                          \
        for (int mt = 0; mt < 4; mt++) {                                           \
            uint32_t sw = sw64(rAoff[mt] + (kb));                                  \
            LDMX4(ah[mt], (uStage) + AHIo + sw);                                   \
            LDMX4(al[mt], (uStage) + ALOo + sw);                                   \
        }                                                                          \
        _Pragma("unroll")                                                          \
        for (int t = 0; t < 4; t++) {                                              \
            uint32_t sw = sw64(rBoff[t] + (kb));                                   \
            LDMX4(bb[t], (uStage) + Bo + sw);                                      \
        }                                                                          \
        _Pragma("unroll")                                                          \
        for (int mt = 0; mt < 4; mt++)                                             \
            _Pragma("unroll")                                                      \
            for (int t = 0; t < 4; t++) {                                          \
                MMA16816(acc[mt][t * 2 + 0], ah[mt], bb[t][0], bb[t][2]);          \
                MMA16816(acc[mt][t * 2 + 1], ah[mt], bb[t][1], bb[t][3]);          \
            }                                                                      \
        _Pragma("unroll")                                                          \
        for (int mt = 0; mt < 4; mt++)                                             \
            _Pragma("unroll")                                                      \
            for (int t = 0; t < 4; t++) {                                          \
                MMA16816(acc[mt][t * 2 + 0], al[mt], bb[t][0], bb[t][2]);          \
                MMA16816(acc[mt][t * 2 + 1], al[mt], bb[t][1], bb[t][3]);          \
            }                                                                      \
    } while (0)

// ---------------- GEMM a16: single fp16 A plane, 128 thr, 3 stages ----------------
__global__ void __launch_bounds__(128, 2)
gemm_a16(const __half* __restrict__ Ah, int lda, const __half* __restrict__ Bw,
         float* __restrict__ C, int ldc, int R, int K, int outSlotBase) {
    extern __shared__ __align__(128) char sm[];
    __shared__ float s_csum[128], s_css[128];
    const uint32_t uS = smem_to_u32(sm);

    const int tid  = threadIdx.x;
    const int wid  = tid >> 5;
    const int lane = tid & 31;
    const int m0     = blockIdx.y * 128;
    const int bnBase = blockIdx.x * 128;
    const int wm = (wid & 1) * 64;
    const int wn = (wid >> 1) * 64;

    s_csum[tid] = 0.f; s_css[tid] = 0.f;
    __syncthreads();

    float acc[4][8][4];
#pragma unroll
    for (int mt = 0; mt < 4; mt++)
#pragma unroll
        for (int nt = 0; nt < 8; nt++)
#pragma unroll
            for (int j = 0; j < 4; j++) acc[mt][nt][j] = 0.f;

    const int nchunks = K >> 5;

    uint32_t rAoff[4], rBoff[4];
#pragma unroll
    for (int mt = 0; mt < 4; mt++) rAoff[mt] = (wm + mt * 16 + (lane & 15)) * 64;
#pragma unroll
    for (int t = 0; t < 4; t++)    rBoff[t]  = (wn + t * 16 + (lane & 15)) * 64;
    const uint32_t kb0 = (lane >> 4) << 4;

    // 512 16B pieces per plane, 128 threads -> 4 pieces each
    int prow[4], pf[4];
    uint32_t swp[4];
#pragma unroll
    for (int j = 0; j < 4; j++) {
        int p = tid + j * 128;
        prow[j] = p >> 2; pf[j] = p & 3;
        swp[j] = sw64(prow[j] * 64 + pf[j] * 16);
    }

    auto issue = [&](int kc) {
        uint32_t uDst = uS + (kc % 3) * STG16;
#pragma unroll
        for (int j = 0; j < 4; j++) {
            cp16(uDst + S16_A + swp[j], Ah + (size_t)(m0 + prow[j]) * lda + kc * 32 + pf[j] * 8);
            cp16(uDst + S16_B + swp[j], Bw + (size_t)(bnBase + prow[j]) * K + kc * 32 + pf[j] * 8);
        }
        CP_COMMIT();
    };

    issue(0);
    if (nchunks > 1) issue(1);

    for (int kc = 0; kc < nchunks; kc++) {
        if (kc + 1 < nchunks) { CP_WAIT(1); } else { CP_WAIT(0); }
        __syncthreads();
        if (kc + 2 < nchunks) issue(kc + 2);
        const uint32_t uStage = uS + (kc % 3) * STG16;
        MMA_CHUNK1(uStage, acc, rAoff, rBoff, kb0);
        MMA_CHUNK1(uStage, acc, rAoff, rBoff, kb0 + 32);
    }

    // epilogue: store C + fused stats (OOB rows zeroed)
#pragma unroll
    for (int mt = 0; mt < 4; mt++) {
        const int row0 = m0 + wm + mt * 16 + (lane >> 2);
#pragma unroll
        for (int nt = 0; nt < 8; nt++) {
            float c0 = acc[mt][nt][0], c1 = acc[mt][nt][1];
            float c2 = acc[mt][nt][2], c3 = acc[mt][nt][3];
            const int cl = wn + nt * 8 + (lane & 3) * 2;
            if (row0 < R)
                *reinterpret_cast<float2*>(C + (size_t)row0 * ldc + bnBase + cl) =
                    make_float2(c0, c1);
            else { c0 = 0.f; c1 = 0.f; }
            if (row0 + 8 < R)
                *reinterpret_cast<float2*>(C + (size_t)(row0 + 8) * ldc + bnBase + cl) =
                    make_float2(c2, c3);
            else { c2 = 0.f; c3 = 0.f; }
            float se = c0 + c2, so = c1 + c3;
            float qe = fmaf(c0, c0, c2 * c2), qo = fmaf(c1, c1, c3 * c3);
#pragma unroll
            for (int off = 16; off >= 4; off >>= 1) {
                se += __shfl_down_sync(0xffffffffu, se, off);
                so += __shfl_down_sync(0xffffffffu, so, off);
                qe += __shfl_down_sync(0xffffffffu, qe, off);
                qo += __shfl_down_sync(0xffffffffu, qo, off);
            }
            if (lane < 4) {
                int c = wn + nt * 8 + lane * 2;
                atomicAdd(&s_csum[c], se); atomicAdd(&s_csum[c + 1], so);
                atomicAdd(&s_css [c], qe); atomicAdd(&s_css [c + 1], qo);
            }
        }
    }
    __syncthreads();
    for (int i = tid; i < 256; i += 128) {
        int c = i & 127;
        int colg = bnBase + c;
        int slot = outSlotBase + (colg >> 8);
        int colIn = colg & 255;
        if (i < 128) atomicAdd(&g_stats[slot][0][colIn], s_csum[c]);
        else         atomicAdd(&g_stats[slot][1][colIn], s_css[c]);
    }
}

// ---------------- GEMM a32: fp32 A + fused BN+ReLU, exact fp16 hi/lo, 128 thr ------------
__global__ void __launch_bounds__(128, 2)
gemm_a32(const float* __restrict__ A, int lda, const __half* __restrict__ Bw,
         float* __restrict__ C, int ldc, int R, int K,
         int inSlot, int outSlotBase,
         const float* __restrict__ Gp, const float* __restrict__ Bp, float Rinv) {
    extern __shared__ __align__(128) char sm[];
    __shared__ float s_scale[256], s_shift[256];
    __shared__ float s_csum[128], s_css[128];
    const uint32_t uS = smem_to_u32(sm);

    const int tid  = threadIdx.x;
    const int wid  = tid >> 5;
    const int lane = tid & 31;
    const int m0     = blockIdx.y * 128;
    const int bnBase = blockIdx.x * 128;
    const int wm = (wid & 1) * 64;
    const int wn = (wid >> 1) * 64;

    for (int c = tid; c < K; c += 128) {
        float mean = g_stats[inSlot][0][c] * Rinv;
        float var  = g_stats[inSlot][1][c] * Rinv - mean * mean;
        float s    = Gp[c] * rsqrtf(var + BN_EPS);
        s_scale[c] = s;
        s_shift[c] = fmaf(-mean, s, Bp[c]);
    }
    s_csum[tid] = 0.f; s_css[tid] = 0.f;
    __syncthreads();

    float acc[4][8][4];
#pragma unroll
    for (int mt = 0; mt < 4; mt++)
#pragma unroll
        for (int nt = 0; nt < 8; nt++)
#pragma unroll
            for (int j = 0; j < 4; j++) acc[mt][nt][j] = 0.f;

    const int nchunks = K >> 5;
    const int agr = m0 + tid;             // one row per thread
    float4 areg[8];

    uint32_t rAoff[4], rBoff[4];
#pragma unroll
    for (int mt = 0; mt < 4; mt++) rAoff[mt] = (wm + mt * 16 + (lane & 15)) * 64;
#pragma unroll
    for (int t = 0; t < 4; t++)    rBoff[t]  = (wn + t * 16 + (lane & 15)) * 64;
    const uint32_t kb0 = (lane >> 4) << 4;

    {
#pragma unroll
        for (int j = 0; j < 4; j++) {
            int p = tid + j * 128;
            int n = p >> 2, f = p & 3;
            uint32_t sw = sw64(n * 64 + f * 16);
            cp16(uS + Bo + sw, Bw + (size_t)(bnBase + n) * K + f * 8);
        }
        CP_COMMIT();
        const float* ap = A + (size_t)agr * lda;
#pragma unroll
        for (int f = 0; f < 8; f++)
            areg[f] = (agr < R) ? *reinterpret_cast<const float4*>(ap + f * 4)
                                : make_float4(0.f, 0.f, 0.f, 0.f);
    }

    for (int kc = 0; kc < nchunks; kc++) {
        const int s = kc & 1;
        const uint32_t uStage = uS + s * STG32;
#pragma unroll
        for (int f = 0; f < 8; f++) {
            float4 v = areg[f];
            if (agr < R) {
                int k = kc * 32 + f * 4;
                v.x = fmaxf(0.f, fmaf(v.x, s_scale[k + 0], s_shift[k + 0]));
                v.y = fmaxf(0.f, fmaf(v.y, s_scale[k + 1], s_shift[k + 1]));
                v.z = fmaxf(0.f, fmaf(v.z, s_scale[k + 2], s_shift[k + 2]));
                v.w = fmaxf(0.f, fmaf(v.w, s_scale[k + 3], s_shift[k + 3]));
            }
            __half2 hxy = __floats2half2_rn(v.x, v.y);
            __half2 hzw = __floats2half2_rn(v.z, v.w);
            __half2 lxy = __floats2half2_rn(v.x - __low2float(hxy), v.y - __high2float(hxy));
            __half2 lzw = __floats2half2_rn(v.z - __low2float(hzw), v.w - __high2float(hzw));
            uint32_t sw = sw64(tid * 64 + f * 8);
            *reinterpret_cast<uint2*>(sm + s * STG32 + AHIo + sw) =
                make_uint2(*reinterpret_cast<uint32_t*>(&hxy),
                           *reinterpret_cast<uint32_t*>(&hzw));
            *reinterpret_cast<uint2*>(sm + s * STG32 + ALOo + sw) =
                make_uint2(*reinterpret_cast<uint32_t*>(&lxy),
                           *reinterpret_cast<uint32_t*>(&lzw));
        }
        if (kc + 1 < nchunks) {
            const float* ap = A + (size_t)agr * lda + (kc + 1) * 32;
#pragma unroll
            for (int f = 0; f < 8; f++)
                areg[f] = (agr < R) ? *reinterpret_cast<const float4*>(ap + f * 4)
                                    : make_float4(0.f, 0.f, 0.f, 0.f);
        }
        CP_WAIT(0);
        __syncthreads();
        if (kc + 1 < nchunks) {
            const uint32_t uN = uS + (s ^ 1) * STG32;
#pragma unroll
            for (int j = 0; j < 4; j++) {
                int p = tid + j * 128;
                int n = p >> 2, f = p & 3;
                uint32_t sw = sw64(n * 64 + f * 16);
                cp16(uN + Bo + sw, Bw + (size_t)(bnBase + n) * K + (kc + 1) * 32 + f * 8);
            }
            CP_COMMIT();
        }
        MMA_CHUNK2(uStage, acc, rAoff, rBoff, kb0);
        MMA_CHUNK2(uStage, acc, rAoff, rBoff, kb0 + 32);
    }

#pragma unroll
    for (int mt = 0; mt < 4; mt++) {
        const int row0 = m0 + wm + mt * 16 + (lane >> 2);
#pragma unroll
        for (int nt = 0; nt < 8; nt++) {
            float c0 = acc[mt][nt][0], c1 = acc[mt][nt][1];
            float c2 = acc[mt][nt][2], c3 = acc[mt][nt][3];
            const int cl = wn + nt * 8 + (lane & 3) * 2;
            if (row0 < R)
                *reinterpret_cast<float2*>(C + (size_t)row0 * ldc + bnBase + cl) =
                    make_float2(c0, c1);
            if (row0 + 8 < R)
                *reinterpret_cast<float2*>(C + (size_t)(row0 + 8) * ldc + bnBase + cl) =
                    make_float2(c2, c3);
            float se = c0 + c2, so = c1 + c3;
            float qe = fmaf(c0, c0, c2 * c2), qo = fmaf(c1, c1, c3 * c3);
#pragma unroll
            for (int off = 16; off >= 4; off >>= 1) {
                se += __shfl_down_sync(0xffffffffu, se, off);
                so += __shfl_down_sync(0xffffffffu, so, off);
                qe += __shfl_down_sync(0xffffffffu, qe, off);
                qo += __shfl_down_sync(0xffffffffu, qo, off);
            }
            if (lane < 4) {
                int c = wn + nt * 8 + lane * 2;
                atomicAdd(&s_csum[c], se); atomicAdd(&s_csum[c + 1], so);
                atomicAdd(&s_css [c], qe); atomicAdd(&s_css [c + 1], qo);
            }
        }
    }
    __syncthreads();
    for (int i = tid; i < 256; i += 128) {
        int c = i & 127;
        int colg = bnBase + c;
        int slot = outSlotBase + (colg >> 8);
        int colIn = colg & 255;
        if (i < 128) atomicAdd(&g_stats[slot][0][colIn], s_csum[c]);
        else         atomicAdd(&g_stats[slot][1][colIn], s_css[c]);
    }
}

// ---------------- consumers ----------------
__device__ __forceinline__ void bn_prep128(float* sc, float* sh, int slot,
                                           const float* G, const float* B, float Rinv) {
    int t = threadIdx.x;
    if (t < 128) {
        float mean = g_stats[slot][0][t] * Rinv;
        float var  = g_stats[slot][1][t] * Rinv - mean * mean;
        float s    = G[t] * rsqrtf(var + BN_EPS);
        sc[t] = s;
        sh[t] = fmaf(-mean, s, B[t]);
    }
    __syncthreads();
}

__global__ void make_edge_new(const float* __restrict__ Y, const float* __restrict__ edge_rep,
                              const float* __restrict__ eps1, int slot,
                              const float* __restrict__ G, const float* __restrict__ B,
                              float Rinv, __half* __restrict__ Ah) {
    __shared__ float sc[128], sh[128];
    bn_prep128(sc, sh, slot, G, B, Rinv);
    int i = blockIdx.x * 256 + threadIdx.x;
    if (i >= NE * 32) return;
    int h = (i & 31) * 4;
    float c = 1.f + eps1[0];
    float4 y = reinterpret_cast<const float4*>(Y)[i];
    float4 e = reinterpret_cast<const float4*>(edge_rep)[i];
    float4 o;
    o.x = fmaf(c, e.x, fmaxf(0.f, fmaf(y.x, sc[h + 0], sh[h + 0])));
    o.y = fmaf(c, e.y, fmaxf(0.f, fmaf(y.y, sc[h + 1], sh[h + 1])));
    o.z = fmaf(c, e.z, fmaxf(0.f, fmaf(y.z, sc[h + 2], sh[h + 2])));
    o.w = fmaf(c, e.w, fmaxf(0.f, fmaf(y.w, sc[h + 3], sh[h + 3])));
    store_h4(Ah, (size_t)i * 4, o);
}

__global__ void edge_out_scatter(const float* __restrict__ Y, const float* __restrict__ Y2,
                                 const int* __restrict__ src, const int* __restrict__ dst,
                                 float* __restrict__ outE, float* __restrict__ S,
                                 int sO, const float* __restrict__ GO, const float* __restrict__ BO,
                                 int sS, const float* __restrict__ GS, const float* __restrict__ BS,
                                 float Rinv) {
    __shared__ float scO[128], shO[128], scS[128], shS[128];
    int t = threadIdx.x;
    if (t < 128) {
        float mean = g_stats[sO][0][t] * Rinv;
        float var  = g_stats[sO][1][t] * Rinv - mean * mean;
        float s    = GO[t] * rsqrtf(var + BN_EPS);
        scO[t] = s; shO[t] = fmaf(-mean, s, BO[t]);
        mean = g_stats[sS][0][t] * Rinv;
        var  = g_stats[sS][1][t] * Rinv - mean * mean;
        s    = GS[t] * rsqrtf(var + BN_EPS);
        scS[t] = s; shS[t] = fmaf(-mean, s, BS[t]);
    }
    __syncthreads();
    int i = blockIdx.x * 256 + threadIdx.x;
    if (i >= NE * 32) return;
    int e = i >> 5, q = i & 31;
    int h = q * 4;
    float4 y = reinterpret_cast<const float4*>(Y)[i];
    float4 o;
    o.x = fmaxf(0.f, fmaf(y.x, scO[h + 0], shO[h + 0]));
    o.y = fmaxf(0.f, fmaf(y.y, scO[h + 1], shO[h + 1]));
    o.z = fmaxf(0.f, fmaf(y.z, scO[h + 2], shO[h + 2]));
    o.w = fmaxf(0.f, fmaf(y.w, scO[h + 3], shO[h + 3]));
    reinterpret_cast<float4*>(outE)[i] = o;
    float4 y2 = reinterpret_cast<const float4*>(Y2)[i];
    float v0 = fmaxf(0.f, fmaf(y2.x, scS[h + 0], shS[h + 0]));
    float v1 = fmaxf(0.f, fmaf(y2.y, scS[h + 1], shS[h + 1]));
    float v2 = fmaxf(0.f, fmaf(y2.z, scS[h + 2], shS[h + 2]));
    float v3 = fmaxf(0.f, fmaf(y2.w, scS[h + 3], shS[h + 3]));
    int s = src[e], d = dst[e];
    red4(S + (size_t)s * HH + h, v0, v1, v2, v3);
    red4(S + (size_t)d * HH + h, v0, v1, v2, v3);
}

__global__ void apply_out(const float* __restrict__ Y, float* __restrict__ out, int nvec,
                          int slot, const float* __restrict__ G, const float* __restrict__ B,
                          float Rinv) {
    __shared__ float sc[128], sh[128];
    bn_prep128(sc, sh, slot, G, B, Rinv);
    int i = blockIdx.x * 256 + threadIdx.x;
    if (i >= nvec) return;
    int h = (i & 31) * 4;
    float4 y = reinterpret_cast<const float4*>(Y)[i];
    float4 o;
    o.x = fmaxf(0.f, fmaf(y.x, sc[h + 0], sh[h + 0]));
    o.y = fmaxf(0.f, fmaf(y.y, sc[h + 1], sh[h + 1]));
    o.z = fmaxf(0.f, fmaf(y.z, sc[h + 2], sh[h + 2]));
    o.w = fmaxf(0.f, fmaf(y.w, sc[h + 3], sh[h + 3]));
    reinterpret_cast<float4*>(out)[i] = o;
}

__global__ void make_node_in(const float* __restrict__ node_rep, const float* __restrict__ degree,
                             const float* __restrict__ S, const float* __restrict__ eps2,
                             __half* __restrict__ Ah) {
    int i = blockIdx.x * blockDim.x + threadIdx.x;
    if (i >= NN * 32) return;
    int n = i >> 5;
    float c = 1.f + eps2[0] - degree[n];
    float4 a = reinterpret_cast<const float4*>(node_rep)[i];
    float4 s = reinterpret_cast<const float4*>(S)[i];
    store_h4(Ah, (size_t)i * 4,
             make_float4(fmaf(c, a.x, s.x), fmaf(c, a.y, s.y),
                         fmaf(c, a.z, s.z), fmaf(c, a.w, s.w)));
}

// ---------------- host ----------------
extern "C" void kernel_launch(void* const* d_in, const int* in_sizes, int n_in,
                              void* d_out, int out_size) {
    const float* node_rep = (const float*)d_in[0];
    const float* edge_rep = (const float*)d_in[1];
    const float* degree   = (const float*)d_in[2];
    const int*   src      = (const int*)  d_in[3];
    const int*   dst      = (const int*)  d_in[4];
    const float* eps1     = (const float*)d_in[5];
    const float* eps2     = (const float*)d_in[6];
    const float* nW1 = (const float*)d_in[7],  *nG1 = (const float*)d_in[8],  *nB1 = (const float*)d_in[9];
    const float* nW2 = (const float*)d_in[10], *nG2 = (const float*)d_in[11], *nB2 = (const float*)d_in[12];
    const float* e0W1 = (const float*)d_in[13], *e0G1 = (const float*)d_in[14], *e0B1 = (const float*)d_in[15];
    const float* e0W2 = (const float*)d_in[16], *e0G2 = (const float*)d_in[17], *e0B2 = (const float*)d_in[18];
    const float* e1W1 = (const float*)d_in[19], *e1G1 = (const float*)d_in[20], *e1B1 = (const float*)d_in[21];
    const float* e1W2 = (const float*)d_in[22], *e1G2 = (const float*)d_in[23], *e1B2 = (const float*)d_in[24];
    const float* e2W1 = (const float*)d_in[25], *e2G1 = (const float*)d_in[26], *e2B1 = (const float*)d_in[27];
    const float* e2W2 = (const float*)d_in[28], *e2G2 = (const float*)d_in[29], *e2B2 = (const float*)d_in[30];

    float* out_node = (float*)d_out;
    float* out_edge = out_node + (size_t)NN * HH;

    cudaFuncSetAttribute(gemm_a16, cudaFuncAttributeMaxDynamicSharedMemorySize, GSMEM16);
    cudaFuncSetAttribute(gemm_a32, cudaFuncAttributeMaxDynamicSharedMemorySize, GSMEM32);

    float *S, *Hb, *Y, *Y2;
    __half *AH, *Wf;
    cudaGetSymbolAddress((void**)&S,  g_S);
    cudaGetSymbolAddress((void**)&Hb, g_Hb);
    cudaGetSymbolAddress((void**)&Y,  g_Y);
    cudaGetSymbolAddress((void**)&Y2, g_Y2);
    cudaGetSymbolAddress((void**)&AH, g_AH);
    cudaGetSymbolAddress((void**)&Wf, g_Wf);

    const int EV = NE * 32;
    const int NV = NN * 32;
    const float RinvE = 1.0f / (float)NE;
    const float RinvN = 1.0f / (float)NN;
    const unsigned gyE = (unsigned)cdivl(NE, 128);
    const unsigned gyN = (unsigned)cdivl(NN, 128);

    init_all<<<(unsigned)cdivl(INIT_TOTAL, 256), 256>>>(e0W1, e0W2, e1W1, e2W1,
                                                        e1W2, e2W2, nW1, nW2);
    scatter_edge<<<(unsigned)cdivl(EV, 256), 256>>>(edge_rep, src, dst, S);
    build_x0<<<(unsigned)cdivl(EV, 256), 256>>>(node_rep, S, src, dst, AH);

    gemm_a16<<<dim3(2, gyE), 128, GSMEM16>>>(AH, H2, Wf + OFF_E0W1, Hb, 512, NE, H2, 0);
    gemm_a32<<<dim3(1, gyE), 128, GSMEM32>>>(Hb, 512, Wf + OFF_E0W2,
                                             Y, 128, NE, H2, 0, 1, e0G1, e0B1, RinvE);
    make_edge_new<<<(unsigned)cdivl(EV, 256), 256>>>(Y, edge_rep, eps1, 1, e0G2, e0B2,
                                                     RinvE, AH);
    gemm_a16<<<dim3(4, gyE), 128, GSMEM16>>>(AH, HH, Wf + OFF_E1W1, Hb, 512, NE, HH, 2);
    gemm_a32<<<dim3(1, gyE), 128, GSMEM32>>>(Hb, 512, Wf + OFF_E1W2,
                                             Y, 128, NE, H2, 2, 4, e1G1, e1B1, RinvE);
    gemm_a32<<<dim3(1, gyE), 128, GSMEM32>>>(Hb + 256, 512, Wf + OFF_E2W2,
                                             Y2, 128, NE, H2, 3, 5, e2G1, e2B1, RinvE);
    zero_f4<<<(unsigned)cdivl((long)NN * HH / 4, 256), 256>>>((float4*)S, NN * HH / 4);
    edge_out_scatter<<<(unsigned)cdivl(EV, 256), 256>>>(Y, Y2, src, dst, out_edge, S,
                                                        4, e1G2, e1B2, 5, e2G2, e2B2, RinvE);
    make_node_in<<<(unsigned)cdivl(NV, 256), 256>>>(node_rep, degree, S, eps2, AH);
    gemm_a16<<<dim3(2, gyN), 128, GSMEM16>>>(AH, HH, Wf + OFF_NW1, Hb, 512, NN, HH, 6);
    gemm_a32<<<dim3(1, gyN), 128, GSMEM32>>>(Hb, 512, Wf + OFF_NW2,
                                             Y, 128, NN, H2, 6, 7, nG1, nB1, RinvN);
    apply_out<<<(unsigned)cdivl(NV, 256), 256>>>(Y, out_node, NV, 7, nG2, nB2, RinvN);
}

// round 14
// speedup vs baseline: 1.3066x; 1.3066x over previous
#include <cuda_runtime.h>
#include <cuda_fp16.h>
#include <cstdint>
#include <cstddef>

#define NN 50000
#define NE 400000
#define HH 128
#define H2 256
#define BN_EPS 1e-5f

// ---------------- scratch ----------------
static __device__ float g_S [(size_t)NN * HH];
static __device__ float g_Hb[(size_t)NE * 512];
static __device__ float g_Y [(size_t)NE * HH];
static __device__ float g_Y2[(size_t)NE * HH];
static __device__ float g_stats[8][2][256];
static __device__ __half g_AH[(size_t)NE * H2];
static __device__ __half g_Wf[294912];

#define OFF_E0W1 0
#define OFF_E0W2 65536
#define OFF_E1W1 98304
#define OFF_E2W1 131072
#define OFF_E1W2 163840
#define OFF_E2W2 196608
#define OFF_NW1  229376
#define OFF_NW2  262144

static inline long cdivl(long a, long b) { return (a + b - 1) / b; }

__device__ __forceinline__ uint32_t smem_to_u32(const void* p) {
    uint32_t a;
    asm("{ .reg .u64 t; cvta.to.shared.u64 t, %1; cvt.u32.u64 %0, t; }" : "=r"(a) : "l"(p));
    return a;
}

#define LDMX4(r, addr) \
    asm volatile("ldmatrix.sync.aligned.m8n8.x4.shared.b16 {%0,%1,%2,%3}, [%4];" \
        : "=r"((r)[0]), "=r"((r)[1]), "=r"((r)[2]), "=r"((r)[3]) : "r"(addr))

#define MMA16816(d, a, b0, b1) \
    asm volatile("mma.sync.aligned.m16n8k16.row.col.f32.f16.f16.f32 " \
        "{%0,%1,%2,%3},{%4,%5,%6,%7},{%8,%9},{%0,%1,%2,%3};" \
        : "+f"((d)[0]), "+f"((d)[1]), "+f"((d)[2]), "+f"((d)[3]) \
        : "r"((a)[0]), "r"((a)[1]), "r"((a)[2]), "r"((a)[3]), "r"(b0), "r"(b1))

__device__ __forceinline__ void cp16(uint32_t dst, const void* src) {
    asm volatile("cp.async.cg.shared.global [%0], [%1], 16;" :: "r"(dst), "l"(src));
}
#define CP_COMMIT() asm volatile("cp.async.commit_group;" ::: "memory")
#define CP_WAIT(n)  asm volatile("cp.async.wait_group %0;" :: "n"(n) : "memory")

__device__ __forceinline__ void red4(float* p, float a, float b, float c, float d) {
    asm volatile("red.global.add.v4.f32 [%0], {%1,%2,%3,%4};"
                 :: "l"(p), "f"(a), "f"(b), "f"(c), "f"(d) : "memory");
}

__device__ __forceinline__ uint32_t sw64(uint32_t off) {
    return off ^ ((off >> 3) & 0x30);
}

__device__ __forceinline__ void store_h4(__half* dst, size_t idx, float4 v) {
    __half2 xy = __floats2half2_rn(v.x, v.y);
    __half2 zw = __floats2half2_rn(v.z, v.w);
    *reinterpret_cast<uint2*>(dst + idx) =
        make_uint2(*reinterpret_cast<uint32_t*>(&xy), *reinterpret_cast<uint32_t*>(&zw));
}

// ---------------- init ----------------
#define NS4 ((NN * HH) / 4)
#define R_STATS 1024
#define R_W 294912
#define INIT_TOTAL (NS4 + R_STATS + R_W)

__global__ void init_all(const float* w0, const float* w1, const float* w2, const float* w3,
                         const float* w4, const float* w5, const float* w6, const float* w7) {
    int gid = blockIdx.x * blockDim.x + threadIdx.x;
    if (gid < NS4) {
        reinterpret_cast<float4*>(g_S)[gid] = make_float4(0.f, 0.f, 0.f, 0.f);
        return;
    }
    gid -= NS4;
    if (gid < R_STATS) {
        reinterpret_cast<float4*>(g_stats)[gid] = make_float4(0.f, 0.f, 0.f, 0.f);
        return;
    }
    gid -= R_STATS;
    if (gid >= R_W) return;
    const float* ws[8] = {w0, w1, w2, w3, w4, w5, w6, w7};
    const int segSize[8] = {65536, 32768, 32768, 32768, 32768, 32768, 32768, 32768};
    const int segK[8]    = {256, 256, 128, 128, 256, 256, 128, 256};
    int seg = 0, base = 0, idx = gid;
#pragma unroll
    for (int s = 0; s < 8; s++) {
        if (idx < segSize[s]) { seg = s; break; }
        idx -= segSize[s];
        base += segSize[s];
    }
    int Kw = segK[seg];
    int Nw = segSize[seg] / Kw;
    int k = idx / Nw, n = idx % Nw;
    g_Wf[base + n * Kw + k] = __float2half_rn(ws[seg][idx]);
}

// ---------------- graph kernels ----------------
__global__ void zero_f4(float4* p, int n4) {
    int i = blockIdx.x * blockDim.x + threadIdx.x;
    if (i < n4) p[i] = make_float4(0.f, 0.f, 0.f, 0.f);
}

__global__ void scatter_edge(const float* __restrict__ edge_rep,
                             const int* __restrict__ src, const int* __restrict__ dst,
                             float* __restrict__ S) {
    int tid = blockIdx.x * blockDim.x + threadIdx.x;
    if (tid >= NE * 32) return;
    int e = tid >> 5, q = tid & 31;
    float4 v = reinterpret_cast<const float4*>(edge_rep)[(size_t)e * 32 + q];
    int s = src[e], d = dst[e];
    red4(S + (size_t)s * HH + q * 4, v.x, v.y, v.z, v.w);
    red4(S + (size_t)d * HH + q * 4, v.x, v.y, v.z, v.w);
}

__global__ void build_x0(const float* __restrict__ node_rep, const float* __restrict__ S,
                         const int* __restrict__ src, const int* __restrict__ dst,
                         __half* __restrict__ Ah) {
    int tid = blockIdx.x * blockDim.x + threadIdx.x;
    if (tid >= NE * 32) return;
    int e = tid >> 5, q = tid & 31;
    int s = src[e], d = dst[e];
    const float4* nr4 = reinterpret_cast<const float4*>(node_rep);
    const float4* S4  = reinterpret_cast<const float4*>(S);
    float4 a0 = nr4[(size_t)s * 32 + q], a1 = nr4[(size_t)d * 32 + q];
    float4 b0 = S4 [(size_t)s * 32 + q], b1 = S4 [(size_t)d * 32 + q];
    store_h4(Ah, (size_t)e * 256 + q * 4,
             make_float4(a0.x + a1.x, a0.y + a1.y, a0.z + a1.z, a0.w + a1.w));
    store_h4(Ah, (size_t)e * 256 + 128 + q * 4,
             make_float4(b0.x + b1.x, b0.y + b1.y, b0.z + b1.z, b0.w + b1.w));
}

// ---------------- MMA core: 8 warps (2m x 4n), warp tile 32x64, single fp16 A ------------
#define S16_A 0
#define S16_B 8192
#define STG16 16384
#define GSMEM16 (3 * STG16)
#define GSMEM32 (2 * STG16)

#define MMA_CHUNK1(uStage, acc, rAoff, rBoff, kb)                                  \
    do {                                                                           \
        uint32_t ah[2][4], bb[4][4];                                               \
        _Pragma("unroll")                                                          \
        for (int mt = 0; mt < 2; mt++) {                                           \
            uint32_t sw = sw64(rAoff[mt] + (kb));                                  \
            LDMX4(ah[mt], (uStage) + S16_A + sw);                                  \
        }                                                                          \
        _Pragma("unroll")                                                          \
        for (int t = 0; t < 4; t++) {                                              \
            uint32_t sw = sw64(rBoff[t] + (kb));                                   \
            LDMX4(bb[t], (uStage) + S16_B + sw);                                   \
        }                                                                          \
        _Pragma("unroll")                                                          \
        for (int mt = 0; mt < 2; mt++)                                             \
            _Pragma("unroll")                                                      \
            for (int t = 0; t < 4; t++) {                                          \
                MMA16816(acc[mt][t * 2 + 0], ah[mt], bb[t][0], bb[t][2]);          \
                MMA16816(acc[mt][t * 2 + 1], ah[mt], bb[t][1], bb[t][3]);          \
            }                                                                      \
    } while (0)

// ---------------- GEMM a16: pre-converted fp16 A, 256 thr, 3 stages ----------------
__global__ void __launch_bounds__(256, 2)
gemm_a16(const __half* __restrict__ Ah, int lda, const __half* __restrict__ Bw,
         float* __restrict__ C, int ldc, int R, int K, int outSlotBase) {
    extern __shared__ __align__(128) char sm[];
    __shared__ float s_csum[128], s_css[128];
    const uint32_t uS = smem_to_u32(sm);

    const int tid  = threadIdx.x;
    const int wid  = tid >> 5;
    const int lane = tid & 31;
    const int m0     = blockIdx.y * 128;
    const int bnBase = blockIdx.x * 128;
    const int wm = (wid & 3) * 32;
    const int wn = (wid >> 2) * 64;

    if (tid < 128) { s_csum[tid] = 0.f; s_css[tid] = 0.f; }
    __syncthreads();

    float acc[2][8][4];
#pragma unroll
    for (int mt = 0; mt < 2; mt++)
#pragma unroll
        for (int nt = 0; nt < 8; nt++)
#pragma unroll
            for (int j = 0; j < 4; j++) acc[mt][nt][j] = 0.f;

    const int nchunks = K >> 5;

    uint32_t rAoff[2], rBoff[4];
#pragma unroll
    for (int mt = 0; mt < 2; mt++) rAoff[mt] = (wm + mt * 16 + (lane & 15)) * 64;
#pragma unroll
    for (int t = 0; t < 4; t++)    rBoff[t]  = (wn + t * 16 + (lane & 15)) * 64;
    const uint32_t kb0 = (lane >> 4) << 4;

    const int p0row = tid >> 2,          p0f = tid & 3;
    const int p1row = (tid + 256) >> 2,  p1f = (tid + 256) & 3;
    const uint32_t sw0 = sw64(p0row * 64 + p0f * 16);
    const uint32_t sw1 = sw64(p1row * 64 + p1f * 16);

    auto issue = [&](int kc) {
        uint32_t uDst = uS + (kc % 3) * STG16;
        cp16(uDst + S16_A + sw0, Ah + (size_t)(m0 + p0row) * lda + kc * 32 + p0f * 8);
        cp16(uDst + S16_B + sw0, Bw + (size_t)(bnBase + p0row) * K + kc * 32 + p0f * 8);
        cp16(uDst + S16_A + sw1, Ah + (size_t)(m0 + p1row) * lda + kc * 32 + p1f * 8);
        cp16(uDst + S16_B + sw1, Bw + (size_t)(bnBase + p1row) * K + kc * 32 + p1f * 8);
        CP_COMMIT();
    };

    issue(0);
    if (nchunks > 1) issue(1);

    for (int kc = 0; kc < nchunks; kc++) {
        if (kc + 1 < nchunks) { CP_WAIT(1); } else { CP_WAIT(0); }
        __syncthreads();
        if (kc + 2 < nchunks) issue(kc + 2);
        const uint32_t uStage = uS + (kc % 3) * STG16;
        MMA_CHUNK1(uStage, acc, rAoff, rBoff, kb0);
        MMA_CHUNK1(uStage, acc, rAoff, rBoff, kb0 + 32);
    }

#pragma unroll
    for (int mt = 0; mt < 2; mt++) {
        const int row0 = m0 + wm + mt * 16 + (lane >> 2);
#pragma unroll
        for (int nt = 0; nt < 8; nt++) {
            float c0 = acc[mt][nt][0], c1 = acc[mt][nt][1];
            float c2 = acc[mt][nt][2], c3 = acc[mt][nt][3];
            const int cl = wn + nt * 8 + (lane & 3) * 2;
            if (row0 < R)
                *reinterpret_cast<float2*>(C + (size_t)row0 * ldc + bnBase + cl) =
                    make_float2(c0, c1);
            else { c0 = 0.f; c1 = 0.f; }
            if (row0 + 8 < R)
                *reinterpret_cast<float2*>(C + (size_t)(row0 + 8) * ldc + bnBase + cl) =
                    make_float2(c2, c3);
            else { c2 = 0.f; c3 = 0.f; }
            float se = c0 + c2, so = c1 + c3;
            float qe = fmaf(c0, c0, c2 * c2), qo = fmaf(c1, c1, c3 * c3);
#pragma unroll
            for (int off = 16; off >= 4; off >>= 1) {
                se += __shfl_down_sync(0xffffffffu, se, off);
                so += __shfl_down_sync(0xffffffffu, so, off);
                qe += __shfl_down_sync(0xffffffffu, qe, off);
                qo += __shfl_down_sync(0xffffffffu, qo, off);
            }
            if (lane < 4) {
                int c = wn + nt * 8 + lane * 2;
                atomicAdd(&s_csum[c], se); atomicAdd(&s_csum[c + 1], so);
                atomicAdd(&s_css [c], qe); atomicAdd(&s_css [c + 1], qo);
            }
        }
    }
    __syncthreads();
    if (tid < 256) {
        int c = tid & 127;
        int colg = bnBase + c;
        int slot = outSlotBase + (colg >> 8);
        int colIn = colg & 255;
        if (tid < 128) atomicAdd(&g_stats[slot][0][colIn], s_csum[c]);
        else           atomicAdd(&g_stats[slot][1][colIn], s_css[c]);
    }
}

// ------- GEMM a32: fp32 A + fused BN+ReLU -> single fp16 plane, 256 thr, 2 stages -------
__global__ void __launch_bounds__(256, 2)
gemm_a32(const float* __restrict__ A, int lda, const __half* __restrict__ Bw,
         float* __restrict__ C, int ldc, int R, int K,
         int inSlot, int outSlotBase,
         const float* __restrict__ Gp, const float* __restrict__ Bp, float Rinv) {
    extern __shared__ __align__(128) char sm[];
    __shared__ float s_scale[256], s_shift[256];
    __shared__ float s_csum[128], s_css[128];
    const uint32_t uS = smem_to_u32(sm);

    const int tid  = threadIdx.x;
    const int wid  = tid >> 5;
    const int lane = tid & 31;
    const int m0     = blockIdx.y * 128;
    const int bnBase = blockIdx.x * 128;
    const int wm = (wid & 3) * 32;
    const int wn = (wid >> 2) * 64;

    for (int c = tid; c < K; c += 256) {
        float mean = g_stats[inSlot][0][c] * Rinv;
        float var  = g_stats[inSlot][1][c] * Rinv - mean * mean;
        float s    = Gp[c] * rsqrtf(var + BN_EPS);
        s_scale[c] = s;
        s_shift[c] = fmaf(-mean, s, Bp[c]);
    }
    if (tid < 128) { s_csum[tid] = 0.f; s_css[tid] = 0.f; }
    __syncthreads();

    float acc[2][8][4];
#pragma unroll
    for (int mt = 0; mt < 2; mt++)
#pragma unroll
        for (int nt = 0; nt < 8; nt++)
#pragma unroll
            for (int j = 0; j < 4; j++) acc[mt][nt][j] = 0.f;

    const int nchunks = K >> 5;
    const int arow_i = tid >> 1;
    const int acb    = (tid & 1) * 16;
    const int agr    = m0 + arow_i;
    float4 areg[4];

    uint32_t rAoff[2], rBoff[4];
#pragma unroll
    for (int mt = 0; mt < 2; mt++) rAoff[mt] = (wm + mt * 16 + (lane & 15)) * 64;
#pragma unroll
    for (int t = 0; t < 4; t++)    rBoff[t]  = (wn + t * 16 + (lane & 15)) * 64;
    const uint32_t kb0 = (lane >> 4) << 4;

    {
#pragma unroll
        for (int j = 0; j < 2; j++) {
            int p = tid + j * 256;
            int n = p >> 2, f = p & 3;
            uint32_t sw = sw64(n * 64 + f * 16);
            cp16(uS + S16_B + sw, Bw + (size_t)(bnBase + n) * K + f * 8);
        }
        CP_COMMIT();
        const float* ap = A + (size_t)agr * lda + acb;
#pragma unroll
        for (int f = 0; f < 4; f++)
            areg[f] = (agr < R) ? *reinterpret_cast<const float4*>(ap + f * 4)
                                : make_float4(0.f, 0.f, 0.f, 0.f);
    }

    for (int kc = 0; kc < nchunks; kc++) {
        const int s = kc & 1;
        const uint32_t uStage = uS + s * STG16;
#pragma unroll
        for (int f = 0; f < 4; f++) {
            float4 v = areg[f];
            if (agr < R) {
                int k = kc * 32 + acb + f * 4;
                v.x = fmaxf(0.f, fmaf(v.x, s_scale[k + 0], s_shift[k + 0]));
                v.y = fmaxf(0.f, fmaf(v.y, s_scale[k + 1], s_shift[k + 1]));
                v.z = fmaxf(0.f, fmaf(v.z, s_scale[k + 2], s_shift[k + 2]));
                v.w = fmaxf(0.f, fmaf(v.w, s_scale[k + 3], s_shift[k + 3]));
            }
            __half2 hxy = __floats2half2_rn(v.x, v.y);
            __half2 hzw = __floats2half2_rn(v.z, v.w);
            uint32_t sw = sw64(arow_i * 64 + (acb + f * 4) * 2);
            *reinterpret_cast<uint2*>(sm + s * STG16 + S16_A + sw) =
                make_uint2(*reinterpret_cast<uint32_t*>(&hxy),
                           *reinterpret_cast<uint32_t*>(&hzw));
        }
        if (kc + 1 < nchunks) {
            const float* ap = A + (size_t)agr * lda + (kc + 1) * 32 + acb;
#pragma unroll
            for (int f = 0; f < 4; f++)
                areg[f] = (agr < R) ? *reinterpret_cast<const float4*>(ap + f * 4)
                                    : make_float4(0.f, 0.f, 0.f, 0.f);
        }
        CP_WAIT(0);
        __syncthreads();
        if (kc + 1 < nchunks) {
            const uint32_t uN = uS + (s ^ 1) * STG16;
#pragma unroll
            for (int j = 0; j < 2; j++) {
                int p = tid + j * 256;
                int n = p >> 2, f = p & 3;
                uint32_t sw = sw64(n * 64 + f * 16);
                cp16(uN + S16_B + sw, Bw + (size_t)(bnBase + n) * K + (kc + 1) * 32 + f * 8);
            }
            CP_COMMIT();
        }
        MMA_CHUNK1(uStage, acc, rAoff, rBoff, kb0);
        MMA_CHUNK1(uStage, acc, rAoff, rBoff, kb0 + 32);
    }

#pragma unroll
    for (int mt = 0; mt < 2; mt++) {
        const int row0 = m0 + wm + mt * 16 + (lane >> 2);
#pragma unroll
        for (int nt = 0; nt < 8; nt++) {
            float c0 = acc[mt][nt][0], c1 = acc[mt][nt][1];
            float c2 = acc[mt][nt][2], c3 = acc[mt][nt][3];
            const int cl = wn + nt * 8 + (lane & 3) * 2;
            if (row0 < R)
                *reinterpret_cast<float2*>(C + (size_t)row0 * ldc + bnBase + cl) =
                    make_float2(c0, c1);
            if (row0 + 8 < R)
                *reinterpret_cast<float2*>(C + (size_t)(row0 + 8) * ldc + bnBase + cl) =
                    make_float2(c2, c3);
            float se = c0 + c2, so = c1 + c3;
            float qe = fmaf(c0, c0, c2 * c2), qo = fmaf(c1, c1, c3 * c3);
#pragma unroll
            for (int off = 16; off >= 4; off >>= 1) {
                se += __shfl_down_sync(0xffffffffu, se, off);
                so += __shfl_down_sync(0xffffffffu, so, off);
                qe += __shfl_down_sync(0xffffffffu, qe, off);
                qo += __shfl_down_sync(0xffffffffu, qo, off);
            }
            if (lane < 4) {
                int c = wn + nt * 8 + lane * 2;
                atomicAdd(&s_csum[c], se); atomicAdd(&s_csum[c + 1], so);
                atomicAdd(&s_css [c], qe); atomicAdd(&s_css [c + 1], qo);
            }
        }
    }
    __syncthreads();
    if (tid < 256) {
        int c = tid & 127;
        int colg = bnBase + c;
        int slot = outSlotBase + (colg >> 8);
        int colIn = colg & 255;
        if (tid < 128) atomicAdd(&g_stats[slot][0][colIn], s_csum[c]);
        else           atomicAdd(&g_stats[slot][1][colIn], s_css[c]);
    }
}

// ---------------- consumers ----------------
__device__ __forceinline__ void bn_prep128(float* sc, float* sh, int slot,
                                           const float* G, const float* B, float Rinv) {
    int t = threadIdx.x;
    if (t < 128) {
        float mean = g_stats[slot][0][t] * Rinv;
        float var  = g_stats[slot][1][t] * Rinv - mean * mean;
        float s    = G[t] * rsqrtf(var + BN_EPS);
        sc[t] = s;
        sh[t] = fmaf(-mean, s, B[t]);
    }
    __syncthreads();
}

__global__ void make_edge_new(const float* __restrict__ Y, const float* __restrict__ edge_rep,
                              const float* __restrict__ eps1, int slot,
                              const float* __restrict__ G, const float* __restrict__ B,
                              float Rinv, __half* __restrict__ Ah) {
    __shared__ float sc[128], sh[128];
    bn_prep128(sc, sh, slot, G, B, Rinv);
    int i = blockIdx.x * 256 + threadIdx.x;
    if (i >= NE * 32) return;
    int h = (i & 31) * 4;
    float c = 1.f + eps1[0];
    float4 y = reinterpret_cast<const float4*>(Y)[i];
    float4 e = reinterpret_cast<const float4*>(edge_rep)[i];
    float4 o;
    o.x = fmaf(c, e.x, fmaxf(0.f, fmaf(y.x, sc[h + 0], sh[h + 0])));
    o.y = fmaf(c, e.y, fmaxf(0.f, fmaf(y.y, sc[h + 1], sh[h + 1])));
    o.z = fmaf(c, e.z, fmaxf(0.f, fmaf(y.z, sc[h + 2], sh[h + 2])));
    o.w = fmaf(c, e.w, fmaxf(0.f, fmaf(y.w, sc[h + 3], sh[h + 3])));
    store_h4(Ah, (size_t)i * 4, o);
}

__global__ void edge_out_scatter(const float* __restrict__ Y, const float* __restrict__ Y2,
                                 const int* __restrict__ src, const int* __restrict__ dst,
                                 float* __restrict__ outE, float* __restrict__ S,
                                 int sO, const float* __restrict__ GO, const float* __restrict__ BO,
                                 int sS, const float* __restrict__ GS, const float* __restrict__ BS,
                                 float Rinv) {
    __shared__ float scO[128], shO[128], scS[128], shS[128];
    int t = threadIdx.x;
    if (t < 128) {
        float mean = g_stats[sO][0][t] * Rinv;
        float var  = g_stats[sO][1][t] * Rinv - mean * mean;
        float s    = GO[t] * rsqrtf(var + BN_EPS);
        scO[t] = s; shO[t] = fmaf(-mean, s, BO[t]);
        mean = g_stats[sS][0][t] * Rinv;
        var  = g_stats[sS][1][t] * Rinv - mean * mean;
        s    = GS[t] * rsqrtf(var + BN_EPS);
        scS[t] = s; shS[t] = fmaf(-mean, s, BS[t]);
    }
    __syncthreads();
    int i = blockIdx.x * 256 + threadIdx.x;
    if (i >= NE * 32) return;
    int e = i >> 5, q = i & 31;
    int h = q * 4;
    float4 y = reinterpret_cast<const float4*>(Y)[i];
    float4 o;
    o.x = fmaxf(0.f, fmaf(y.x, scO[h + 0], shO[h + 0]));
    o.y = fmaxf(0.f, fmaf(y.y, scO[h + 1], shO[h + 1]));
    o.z = fmaxf(0.f, fmaf(y.z, scO[h + 2], shO[h + 2]));
    o.w = fmaxf(0.f, fmaf(y.w, scO[h + 3], shO[h + 3]));
    reinterpret_cast<float4*>(outE)[i] = o;
    float4 y2 = reinterpret_cast<const float4*>(Y2)[i];
    float v0 = fmaxf(0.f, fmaf(y2.x, scS[h + 0], shS[h + 0]));
    float v1 = fmaxf(0.f, fmaf(y2.y, scS[h + 1], shS[h + 1]));
    float v2 = fmaxf(0.f, fmaf(y2.z, scS[h + 2], shS[h + 2]));
    float v3 = fmaxf(0.f, fmaf(y2.w, scS[h + 3], shS[h + 3]));
    int s = src[e], d = dst[e];
    red4(S + (size_t)s * HH + h, v0, v1, v2, v3);
    red4(S + (size_t)d * HH + h, v0, v1, v2, v3);
}

__global__ void apply_out(const float* __restrict__ Y, float* __restrict__ out, int nvec,
                          int slot, const float* __restrict__ G, const float* __restrict__ B,
                          float Rinv) {
    __shared__ float sc[128], sh[128];
    bn_prep128(sc, sh, slot, G, B, Rinv);
    int i = blockIdx.x * 256 + threadIdx.x;
    if (i >= nvec) return;
    int h = (i & 31) * 4;
    float4 y = reinterpret_cast<const float4*>(Y)[i];
    float4 o;
    o.x = fmaxf(0.f, fmaf(y.x, sc[h + 0], sh[h + 0]));
    o.y = fmaxf(0.f, fmaf(y.y, sc[h + 1], sh[h + 1]));
    o.z = fmaxf(0.f, fmaf(y.z, sc[h + 2], sh[h + 2]));
    o.w = fmaxf(0.f, fmaf(y.w, sc[h + 3], sh[h + 3]));
    reinterpret_cast<float4*>(out)[i] = o;
}

__global__ void make_node_in(const float* __restrict__ node_rep, const float* __restrict__ degree,
                             const float* __restrict__ S, const float* __restrict__ eps2,
                             __half* __restrict__ Ah) {
    int i = blockIdx.x * blockDim.x + threadIdx.x;
    if (i >= NN * 32) return;
    int n = i >> 5;
    float c = 1.f + eps2[0] - degree[n];
    float4 a = reinterpret_cast<const float4*>(node_rep)[i];
    float4 s = reinterpret_cast<const float4*>(S)[i];
    store_h4(Ah, (size_t)i * 4,
             make_float4(fmaf(c, a.x, s.x), fmaf(c, a.y, s.y),
                         fmaf(c, a.z, s.z), fmaf(c, a.w, s.w)));
}

// ---------------- host ----------------
extern "C" void kernel_launch(void* const* d_in, const int* in_sizes, int n_in,
                              void* d_out, int out_size) {
    const float* node_rep = (const float*)d_in[0];
    const float* edge_rep = (const float*)d_in[1];
    const float* degree   = (const float*)d_in[2];
    const int*   src      = (const int*)  d_in[3];
    const int*   dst      = (const int*)  d_in[4];
    const float* eps1     = (const float*)d_in[5];
    const float* eps2     = (const float*)d_in[6];
    const float* nW1 = (const float*)d_in[7],  *nG1 = (const float*)d_in[8],  *nB1 = (const float*)d_in[9];
    const float* nW2 = (const float*)d_in[10], *nG2 = (const float*)d_in[11], *nB2 = (const float*)d_in[12];
    const float* e0W1 = (const float*)d_in[13], *e0G1 = (const float*)d_in[14], *e0B1 = (const float*)d_in[15];
    const float* e0W2 = (const float*)d_in[16], *e0G2 = (const float*)d_in[17], *e0B2 = (const float*)d_in[18];
    const float* e1W1 = (const float*)d_in[19], *e1G1 = (const float*)d_in[20], *e1B1 = (const float*)d_in[21];
    const float* e1W2 = (const float*)d_in[22], *e1G2 = (const float*)d_in[23], *e1B2 = (const float*)d_in[24];
    const float* e2W1 = (const float*)d_in[25], *e2G1 = (const float*)d_in[26], *e2B1 = (const float*)d_in[27];
    const float* e2W2 = (const float*)d_in[28], *e2G2 = (const float*)d_in[29], *e2B2 = (const float*)d_in[30];

    float* out_node = (float*)d_out;
    float* out_edge = out_node + (size_t)NN * HH;

    cudaFuncSetAttribute(gemm_a16, cudaFuncAttributeMaxDynamicSharedMemorySize, GSMEM16);
    cudaFuncSetAttribute(gemm_a32, cudaFuncAttributeMaxDynamicSharedMemorySize, GSMEM32);

    float *S, *Hb, *Y, *Y2;
    __half *AH, *Wf;
    cudaGetSymbolAddress((void**)&S,  g_S);
    cudaGetSymbolAddress((void**)&Hb, g_Hb);
    cudaGetSymbolAddress((void**)&Y,  g_Y);
    cudaGetSymbolAddress((void**)&Y2, g_Y2);
    cudaGetSymbolAddress((void**)&AH, g_AH);
    cudaGetSymbolAddress((void**)&Wf, g_Wf);

    const int EV = NE * 32;
    const int NV = NN * 32;
    const float RinvE = 1.0f / (float)NE;
    const float RinvN = 1.0f / (float)NN;
    const unsigned gyE = (unsigned)cdivl(NE, 128);
    const unsigned gyN = (unsigned)cdivl(NN, 128);

    init_all<<<(unsigned)cdivl(INIT_TOTAL, 256), 256>>>(e0W1, e0W2, e1W1, e2W1,
                                                        e1W2, e2W2, nW1, nW2);
    scatter_edge<<<(unsigned)cdivl(EV, 256), 256>>>(edge_rep, src, dst, S);
    build_x0<<<(unsigned)cdivl(EV, 256), 256>>>(node_rep, S, src, dst, AH);

    gemm_a16<<<dim3(2, gyE), 256, GSMEM16>>>(AH, H2, Wf + OFF_E0W1, Hb, 512, NE, H2, 0);
    gemm_a32<<<dim3(1, gyE), 256, GSMEM32>>>(Hb, 512, Wf + OFF_E0W2,
                                             Y, 128, NE, H2, 0, 1, e0G1, e0B1, RinvE);
    make_edge_new<<<(unsigned)cdivl(EV, 256), 256>>>(Y, edge_rep, eps1, 1, e0G2, e0B2,
                                                     RinvE, AH);
    gemm_a16<<<dim3(4, gyE), 256, GSMEM16>>>(AH, HH, Wf + OFF_E1W1, Hb, 512, NE, HH, 2);
    gemm_a32<<<dim3(1, gyE), 256, GSMEM32>>>(Hb, 512, Wf + OFF_E1W2,
                                             Y, 128, NE, H2, 2, 4, e1G1, e1B1, RinvE);
    gemm_a32<<<dim3(1, gyE), 256, GSMEM32>>>(Hb + 256, 512, Wf + OFF_E2W2,
                                             Y2, 128, NE, H2, 3, 5, e2G1, e2B1, RinvE);
    zero_f4<<<(unsigned)cdivl((long)NN * HH / 4, 256), 256>>>((float4*)S, NN * HH / 4);
    edge_out_scatter<<<(unsigned)cdivl(EV, 256), 256>>>(Y, Y2, src, dst, out_edge, S,
                                                        4, e1G2, e1B2, 5, e2G2, e2B2, RinvE);
    make_node_in<<<(unsigned)cdivl(NV, 256), 256>>>(node_rep, degree, S, eps2, AH);
    gemm_a16<<<dim3(2, gyN), 256, GSMEM16>>>(AH, HH, Wf + OFF_NW1, Hb, 512, NN, HH, 6);
    gemm_a32<<<dim3(1, gyN), 256, GSMEM32>>>(Hb, 512, Wf + OFF_NW2,
                                             Y, 128, NN, H2, 6, 7, nG1, nB1, RinvN);
    apply_out<<<(unsigned)cdivl(NV, 256), 256>>>(Y, out_node, NV, 7, nG2, nB2, RinvN);
}

// round 15
// speedup vs baseline: 1.3418x; 1.0270x over previous
#include <cuda_runtime.h>
#include <cuda_fp16.h>
#include <cstdint>
#include <cstddef>

#define NN 50000
#define NE 400000
#define HH 128
#define H2 256
#define BN_EPS 1e-5f

// ---------------- scratch ----------------
static __device__ float g_S [(size_t)NN * HH];
static __device__ float g_Hb[(size_t)NE * 512];
static __device__ float g_Y [(size_t)NE * HH];
static __device__ float g_Y2[(size_t)NE * HH];
static __device__ float g_stats[8][2][256];
static __device__ __half g_AH[(size_t)NE * H2];
static __device__ __half g_Wf[294912];

#define OFF_E0W1 0
#define OFF_E0W2 65536
#define OFF_E1W1 98304
#define OFF_E2W1 131072
#define OFF_E1W2 163840
#define OFF_E2W2 196608
#define OFF_NW1  229376
#define OFF_NW2  262144

static inline long cdivl(long a, long b) { return (a + b - 1) / b; }

__device__ __forceinline__ uint32_t smem_to_u32(const void* p) {
    uint32_t a;
    asm("{ .reg .u64 t; cvta.to.shared.u64 t, %1; cvt.u32.u64 %0, t; }" : "=r"(a) : "l"(p));
    return a;
}

#define LDMX4(r, addr) \
    asm volatile("ldmatrix.sync.aligned.m8n8.x4.shared.b16 {%0,%1,%2,%3}, [%4];" \
        : "=r"((r)[0]), "=r"((r)[1]), "=r"((r)[2]), "=r"((r)[3]) : "r"(addr))

#define MMA16816(d, a, b0, b1) \
    asm volatile("mma.sync.aligned.m16n8k16.row.col.f32.f16.f16.f32 " \
        "{%0,%1,%2,%3},{%4,%5,%6,%7},{%8,%9},{%0,%1,%2,%3};" \
        : "+f"((d)[0]), "+f"((d)[1]), "+f"((d)[2]), "+f"((d)[3]) \
        : "r"((a)[0]), "r"((a)[1]), "r"((a)[2]), "r"((a)[3]), "r"(b0), "r"(b1))

__device__ __forceinline__ void cp16(uint32_t dst, const void* src) {
    asm volatile("cp.async.cg.shared.global [%0], [%1], 16;" :: "r"(dst), "l"(src));
}
#define CP_COMMIT() asm volatile("cp.async.commit_group;" ::: "memory")
#define CP_WAIT(n)  asm volatile("cp.async.wait_group %0;" :: "n"(n) : "memory")

__device__ __forceinline__ void red4(float* p, float a, float b, float c, float d) {
    asm volatile("red.global.add.v4.f32 [%0], {%1,%2,%3,%4};"
                 :: "l"(p), "f"(a), "f"(b), "f"(c), "f"(d) : "memory");
}

__device__ __forceinline__ uint32_t sw64(uint32_t off)  { return off ^ ((off >> 3) & 0x30); }
__device__ __forceinline__ uint32_t sw128(uint32_t off) { return off ^ ((off >> 3) & 0x70); }

__device__ __forceinline__ void store_h4(__half* dst, size_t idx, float4 v) {
    __half2 xy = __floats2half2_rn(v.x, v.y);
    __half2 zw = __floats2half2_rn(v.z, v.w);
    *reinterpret_cast<uint2*>(dst + idx) =
        make_uint2(*reinterpret_cast<uint32_t*>(&xy), *reinterpret_cast<uint32_t*>(&zw));
}

// ---------------- init ----------------
#define NS4 ((NN * HH) / 4)
#define R_STATS 1024
#define R_W 294912
#define INIT_TOTAL (NS4 + R_STATS + R_W)

__global__ void init_all(const float* w0, const float* w1, const float* w2, const float* w3,
                         const float* w4, const float* w5, const float* w6, const float* w7) {
    int gid = blockIdx.x * blockDim.x + threadIdx.x;
    if (gid < NS4) {
        reinterpret_cast<float4*>(g_S)[gid] = make_float4(0.f, 0.f, 0.f, 0.f);
        return;
    }
    gid -= NS4;
    if (gid < R_STATS) {
        reinterpret_cast<float4*>(g_stats)[gid] = make_float4(0.f, 0.f, 0.f, 0.f);
        return;
    }
    gid -= R_STATS;
    if (gid >= R_W) return;
    const float* ws[8] = {w0, w1, w2, w3, w4, w5, w6, w7};
    const int segSize[8] = {65536, 32768, 32768, 32768, 32768, 32768, 32768, 32768};
    const int segK[8]    = {256, 256, 128, 128, 256, 256, 128, 256};
    int seg = 0, base = 0, idx = gid;
#pragma unroll
    for (int s = 0; s < 8; s++) {
        if (idx < segSize[s]) { seg = s; break; }
        idx -= segSize[s];
        base += segSize[s];
    }
    int Kw = segK[seg];
    int Nw = segSize[seg] / Kw;
    int k = idx / Nw, n = idx % Nw;
    g_Wf[base + n * Kw + k] = __float2half_rn(ws[seg][idx]);
}

// ---------------- graph kernels ----------------
__global__ void zero_f4(float4* p, int n4) {
    int i = blockIdx.x * blockDim.x + threadIdx.x;
    if (i < n4) p[i] = make_float4(0.f, 0.f, 0.f, 0.f);
}

__global__ void scatter_edge(const float* __restrict__ edge_rep,
                             const int* __restrict__ src, const int* __restrict__ dst,
                             float* __restrict__ S) {
    int tid = blockIdx.x * blockDim.x + threadIdx.x;
    if (tid >= NE * 32) return;
    int e = tid >> 5, q = tid & 31;
    float4 v = reinterpret_cast<const float4*>(edge_rep)[(size_t)e * 32 + q];
    int s = src[e], d = dst[e];
    red4(S + (size_t)s * HH + q * 4, v.x, v.y, v.z, v.w);
    red4(S + (size_t)d * HH + q * 4, v.x, v.y, v.z, v.w);
}

__global__ void build_x0(const float* __restrict__ node_rep, const float* __restrict__ S,
                         const int* __restrict__ src, const int* __restrict__ dst,
                         __half* __restrict__ Ah) {
    int tid = blockIdx.x * blockDim.x + threadIdx.x;
    if (tid >= NE * 32) return;
    int e = tid >> 5, q = tid & 31;
    int s = src[e], d = dst[e];
    const float4* nr4 = reinterpret_cast<const float4*>(node_rep);
    const float4* S4  = reinterpret_cast<const float4*>(S);
    float4 a0 = nr4[(size_t)s * 32 + q], a1 = nr4[(size_t)d * 32 + q];
    float4 b0 = S4 [(size_t)s * 32 + q], b1 = S4 [(size_t)d * 32 + q];
    store_h4(Ah, (size_t)e * 256 + q * 4,
             make_float4(a0.x + a1.x, a0.y + a1.y, a0.z + a1.z, a0.w + a1.w));
    store_h4(Ah, (size_t)e * 256 + 128 + q * 4,
             make_float4(b0.x + b1.x, b0.y + b1.y, b0.z + b1.z, b0.w + b1.w));
}

// ---------------- a16 core: BK=64, SW128 rows, 8 warps (4m x 2n), tile 32x64 -------------
#define A64_A 0
#define A64_B 16384
#define STG64 32768
#define GSMEM16 (3 * STG64)

#define MMA_CHUNK64(uStage, acc, rAoff, rBoff, kb)                                 \
    do {                                                                           \
        uint32_t ah[2][4], bb[4][4];                                               \
        _Pragma("unroll")                                                          \
        for (int mt = 0; mt < 2; mt++) {                                           \
            uint32_t sw = sw128(rAoff[mt] + (kb));                                 \
            LDMX4(ah[mt], (uStage) + A64_A + sw);                                  \
        }                                                                          \
        _Pragma("unroll")                                                          \
        for (int t = 0; t < 4; t++) {                                              \
            uint32_t sw = sw128(rBoff[t] + (kb));                                  \
            LDMX4(bb[t], (uStage) + A64_B + sw);                                   \
        }                                                                          \
        _Pragma("unroll")                                                          \
        for (int mt = 0; mt < 2; mt++)                                             \
            _Pragma("unroll")                                                      \
            for (int t = 0; t < 4; t++) {                                          \
                MMA16816(acc[mt][t * 2 + 0], ah[mt], bb[t][0], bb[t][2]);          \
                MMA16816(acc[mt][t * 2 + 1], ah[mt], bb[t][1], bb[t][3]);          \
            }                                                                      \
    } while (0)

__global__ void __launch_bounds__(256, 2)
gemm_a16(const __half* __restrict__ Ah, int lda, const __half* __restrict__ Bw,
         float* __restrict__ C, int ldc, int R, int K, int outSlotBase) {
    extern __shared__ __align__(128) char sm[];
    __shared__ float s_csum[128], s_css[128];
    const uint32_t uS = smem_to_u32(sm);

    const int tid  = threadIdx.x;
    const int wid  = tid >> 5;
    const int lane = tid & 31;
    const int m0     = blockIdx.y * 128;
    const int bnBase = blockIdx.x * 128;
    const int wm = (wid & 3) * 32;
    const int wn = (wid >> 2) * 64;

    if (tid < 128) { s_csum[tid] = 0.f; s_css[tid] = 0.f; }
    __syncthreads();

    float acc[2][8][4];
#pragma unroll
    for (int mt = 0; mt < 2; mt++)
#pragma unroll
        for (int nt = 0; nt < 8; nt++)
#pragma unroll
            for (int j = 0; j < 4; j++) acc[mt][nt][j] = 0.f;

    const int nchunks = K >> 6;   // BK=64

    uint32_t rAoff[2], rBoff[4];
#pragma unroll
    for (int mt = 0; mt < 2; mt++) rAoff[mt] = (wm + mt * 16 + (lane & 15)) * 128;
#pragma unroll
    for (int t = 0; t < 4; t++)    rBoff[t]  = (wn + t * 16 + (lane & 15)) * 128;
    const uint32_t kb0 = (lane >> 4) << 4;

    // 1024 16B pieces per plane, 256 threads -> 4 each
    uint32_t swp[4];
    int prow[4], pf[4];
#pragma unroll
    for (int j = 0; j < 4; j++) {
        int p = tid + j * 256;
        prow[j] = p >> 3; pf[j] = p & 7;
        swp[j] = sw128(prow[j] * 128 + pf[j] * 16);
    }

    auto issue = [&](int kc) {
        uint32_t uDst = uS + (kc % 3) * STG64;
#pragma unroll
        for (int j = 0; j < 4; j++) {
            cp16(uDst + A64_A + swp[j], Ah + (size_t)(m0 + prow[j]) * lda + kc * 64 + pf[j] * 8);
            cp16(uDst + A64_B + swp[j], Bw + (size_t)(bnBase + prow[j]) * K + kc * 64 + pf[j] * 8);
        }
        CP_COMMIT();
    };

    issue(0);
    if (nchunks > 1) issue(1);

    for (int kc = 0; kc < nchunks; kc++) {
        if (kc + 1 < nchunks) { CP_WAIT(1); } else { CP_WAIT(0); }
        __syncthreads();
        if (kc + 2 < nchunks) issue(kc + 2);
        const uint32_t uStage = uS + (kc % 3) * STG64;
        MMA_CHUNK64(uStage, acc, rAoff, rBoff, kb0);
        MMA_CHUNK64(uStage, acc, rAoff, rBoff, kb0 + 32);
        MMA_CHUNK64(uStage, acc, rAoff, rBoff, kb0 + 64);
        MMA_CHUNK64(uStage, acc, rAoff, rBoff, kb0 + 96);
    }

#pragma unroll
    for (int mt = 0; mt < 2; mt++) {
        const int row0 = m0 + wm + mt * 16 + (lane >> 2);
#pragma unroll
        for (int nt = 0; nt < 8; nt++) {
            float c0 = acc[mt][nt][0], c1 = acc[mt][nt][1];
            float c2 = acc[mt][nt][2], c3 = acc[mt][nt][3];
            const int cl = wn + nt * 8 + (lane & 3) * 2;
            if (row0 < R)
                *reinterpret_cast<float2*>(C + (size_t)row0 * ldc + bnBase + cl) =
                    make_float2(c0, c1);
            else { c0 = 0.f; c1 = 0.f; }
            if (row0 + 8 < R)
                *reinterpret_cast<float2*>(C + (size_t)(row0 + 8) * ldc + bnBase + cl) =
                    make_float2(c2, c3);
            else { c2 = 0.f; c3 = 0.f; }
            float se = c0 + c2, so = c1 + c3;
            float qe = fmaf(c0, c0, c2 * c2), qo = fmaf(c1, c1, c3 * c3);
#pragma unroll
            for (int off = 16; off >= 4; off >>= 1) {
                se += __shfl_down_sync(0xffffffffu, se, off);
                so += __shfl_down_sync(0xffffffffu, so, off);
                qe += __shfl_down_sync(0xffffffffu, qe, off);
                qo += __shfl_down_sync(0xffffffffu, qo, off);
            }
            if (lane < 4) {
                int c = wn + nt * 8 + lane * 2;
                atomicAdd(&s_csum[c], se); atomicAdd(&s_csum[c + 1], so);
                atomicAdd(&s_css [c], qe); atomicAdd(&s_css [c + 1], qo);
            }
        }
    }
    __syncthreads();
    if (tid < 256) {
        int c = tid & 127;
        int colg = bnBase + c;
        int slot = outSlotBase + (colg >> 8);
        int colIn = colg & 255;
        if (tid < 128) atomicAdd(&g_stats[slot][0][colIn], s_csum[c]);
        else           atomicAdd(&g_stats[slot][1][colIn], s_css[c]);
    }
}

// ------- GEMM a32: fp32 A + fused BN+ReLU -> single fp16 plane, BK=32, 2 stages -------
#define S16_A 0
#define S16_B 8192
#define STG16 16384
#define GSMEM32 (2 * STG16)

#define MMA_CHUNK1(uStage, acc, rAoff, rBoff, kb)                                  \
    do {                                                                           \
        uint32_t ah[2][4], bb[4][4];                                               \
        _Pragma("unroll")                                                          \
        for (int mt = 0; mt < 2; mt++) {                                           \
            uint32_t sw = sw64(rAoff[mt] + (kb));                                  \
            LDMX4(ah[mt], (uStage) + S16_A + sw);                                  \
        }                                                                          \
        _Pragma("unroll")                                                          \
        for (int t = 0; t < 4; t++) {                                              \
            uint32_t sw = sw64(rBoff[t] + (kb));                                   \
            LDMX4(bb[t], (uStage) + S16_B + sw);                                   \
        }                                                                          \
        _Pragma("unroll")                                                          \
        for (int mt = 0; mt < 2; mt++)                                             \
            _Pragma("unroll")                                                      \
            for (int t = 0; t < 4; t++) {                                          \
                MMA16816(acc[mt][t * 2 + 0], ah[mt], bb[t][0], bb[t][2]);          \
                MMA16816(acc[mt][t * 2 + 1], ah[mt], bb[t][1], bb[t][3]);          \
            }                                                                      \
    } while (0)

__global__ void __launch_bounds__(256, 2)
gemm_a32(const float* __restrict__ A, int lda, const __half* __restrict__ Bw,
         float* __restrict__ C, int ldc, int R, int K,
         int inSlot, int outSlotBase,
         const float* __restrict__ Gp, const float* __restrict__ Bp, float Rinv) {
    extern __shared__ __align__(128) char sm[];
    __shared__ float s_scale[256], s_shift[256];
    __shared__ float s_csum[128], s_css[128];
    const uint32_t uS = smem_to_u32(sm);

    const int tid  = threadIdx.x;
    const int wid  = tid >> 5;
    const int lane = tid & 31;
    const int m0     = blockIdx.y * 128;
    const int bnBase = blockIdx.x * 128;
    const int wm = (wid & 3) * 32;
    const int wn = (wid >> 2) * 64;

    for (int c = tid; c < K; c += 256) {
        float mean = g_stats[inSlot][0][c] * Rinv;
        float var  = g_stats[inSlot][1][c] * Rinv - mean * mean;
        float s    = Gp[c] * rsqrtf(var + BN_EPS);
        s_scale[c] = s;
        s_shift[c] = fmaf(-mean, s, Bp[c]);
    }
    if (tid < 128) { s_csum[tid] = 0.f; s_css[tid] = 0.f; }
    __syncthreads();

    float acc[2][8][4];
#pragma unroll
    for (int mt = 0; mt < 2; mt++)
#pragma unroll
        for (int nt = 0; nt < 8; nt++)
#pragma unroll
            for (int j = 0; j < 4; j++) acc[mt][nt][j] = 0.f;

    const int nchunks = K >> 5;
    const int arow_i = tid >> 1;
    const int acb    = (tid & 1) * 16;
    const int agr    = m0 + arow_i;
    float4 areg[4];

    uint32_t rAoff[2], rBoff[4];
#pragma unroll
    for (int mt = 0; mt < 2; mt++) rAoff[mt] = (wm + mt * 16 + (lane & 15)) * 64;
#pragma unroll
    for (int t = 0; t < 4; t++)    rBoff[t]  = (wn + t * 16 + (lane & 15)) * 64;
    const uint32_t kb0 = (lane >> 4) << 4;

    {
#pragma unroll
        for (int j = 0; j < 2; j++) {
            int p = tid + j * 256;
            int n = p >> 2, f = p & 3;
            uint32_t sw = sw64(n * 64 + f * 16);
            cp16(uS + S16_B + sw, Bw + (size_t)(bnBase + n) * K + f * 8);
        }
        CP_COMMIT();
        const float* ap = A + (size_t)agr * lda + acb;
#pragma unroll
        for (int f = 0; f < 4; f++)
            areg[f] = (agr < R) ? *reinterpret_cast<const float4*>(ap + f * 4)
                                : make_float4(0.f, 0.f, 0.f, 0.f);
    }

    for (int kc = 0; kc < nchunks; kc++) {
        const int s = kc & 1;
        const uint32_t uStage = uS + s * STG16;
#pragma unroll
        for (int f = 0; f < 4; f++) {
            float4 v = areg[f];
            if (agr < R) {
                int k = kc * 32 + acb + f * 4;
                v.x = fmaxf(0.f, fmaf(v.x, s_scale[k + 0], s_shift[k + 0]));
                v.y = fmaxf(0.f, fmaf(v.y, s_scale[k + 1], s_shift[k + 1]));
                v.z = fmaxf(0.f, fmaf(v.z, s_scale[k + 2], s_shift[k + 2]));
                v.w = fmaxf(0.f, fmaf(v.w, s_scale[k + 3], s_shift[k + 3]));
            }
            __half2 hxy = __floats2half2_rn(v.x, v.y);
            __half2 hzw = __floats2half2_rn(v.z, v.w);
            uint32_t sw = sw64(arow_i * 64 + (acb + f * 4) * 2);
            *reinterpret_cast<uint2*>(sm + s * STG16 + S16_A + sw) =
                make_uint2(*reinterpret_cast<uint32_t*>(&hxy),
                           *reinterpret_cast<uint32_t*>(&hzw));
        }
        if (kc + 1 < nchunks) {
            const float* ap = A + (size_t)agr * lda + (kc + 1) * 32 + acb;
#pragma unroll
            for (int f = 0; f < 4; f++)
                areg[f] = (agr < R) ? *reinterpret_cast<const float4*>(ap + f * 4)
                                    : make_float4(0.f, 0.f, 0.f, 0.f);
        }
        CP_WAIT(0);
        __syncthreads();
        if (kc + 1 < nchunks) {
            const uint32_t uN = uS + (s ^ 1) * STG16;
#pragma unroll
            for (int j = 0; j < 2; j++) {
                int p = tid + j * 256;
                int n = p >> 2, f = p & 3;
                uint32_t sw = sw64(n * 64 + f * 16);
                cp16(uN + S16_B + sw, Bw + (size_t)(bnBase + n) * K + (kc + 1) * 32 + f * 8);
            }
            CP_COMMIT();
        }
        MMA_CHUNK1(uStage, acc, rAoff, rBoff, kb0);
        MMA_CHUNK1(uStage, acc, rAoff, rBoff, kb0 + 32);
    }

#pragma unroll
    for (int mt = 0; mt < 2; mt++) {
        const int row0 = m0 + wm + mt * 16 + (lane >> 2);
#pragma unroll
        for (int nt = 0; nt < 8; nt++) {
            float c0 = acc[mt][nt][0], c1 = acc[mt][nt][1];
            float c2 = acc[mt][nt][2], c3 = acc[mt][nt][3];
            const int cl = wn + nt * 8 + (lane & 3) * 2;
            if (row0 < R)
                *reinterpret_cast<float2*>(C + (size_t)row0 * ldc + bnBase + cl) =
                    make_float2(c0, c1);
            if (row0 + 8 < R)
                *reinterpret_cast<float2*>(C + (size_t)(row0 + 8) * ldc + bnBase + cl) =
                    make_float2(c2, c3);
            float se = c0 + c2, so = c1 + c3;
            float qe = fmaf(c0, c0, c2 * c2), qo = fmaf(c1, c1, c3 * c3);
#pragma unroll
            for (int off = 16; off >= 4; off >>= 1) {
                se += __shfl_down_sync(0xffffffffu, se, off);
                so += __shfl_down_sync(0xffffffffu, so, off);
                qe += __shfl_down_sync(0xffffffffu, qe, off);
                qo += __shfl_down_sync(0xffffffffu, qo, off);
            }
            if (lane < 4) {
                int c = wn + nt * 8 + lane * 2;
                atomicAdd(&s_csum[c], se); atomicAdd(&s_csum[c + 1], so);
                atomicAdd(&s_css [c], qe); atomicAdd(&s_css [c + 1], qo);
            }
        }
    }
    __syncthreads();
    if (tid < 256) {
        int c = tid & 127;
        int colg = bnBase + c;
        int slot = outSlotBase + (colg >> 8);
        int colIn = colg & 255;
        if (tid < 128) atomicAdd(&g_stats[slot][0][colIn], s_csum[c]);
        else           atomicAdd(&g_stats[slot][1][colIn], s_css[c]);
    }
}

// ---------------- consumers ----------------
__device__ __forceinline__ void bn_prep128(float* sc, float* sh, int slot,
                                           const float* G, const float* B, float Rinv) {
    int t = threadIdx.x;
    if (t < 128) {
        float mean = g_stats[slot][0][t] * Rinv;
        float var  = g_stats[slot][1][t] * Rinv - mean * mean;
        float s    = G[t] * rsqrtf(var + BN_EPS);
        sc[t] = s;
        sh[t] = fmaf(-mean, s, B[t]);
    }
    __syncthreads();
}

__global__ void make_edge_new(const float* __restrict__ Y, const float* __restrict__ edge_rep,
                              const float* __restrict__ eps1, int slot,
                              const float* __restrict__ G, const float* __restrict__ B,
                              float Rinv, __half* __restrict__ Ah) {
    __shared__ float sc[128], sh[128];
    bn_prep128(sc, sh, slot, G, B, Rinv);
    int i = blockIdx.x * 256 + threadIdx.x;
    if (i >= NE * 32) return;
    int h = (i & 31) * 4;
    float c = 1.f + eps1[0];
    float4 y = reinterpret_cast<const float4*>(Y)[i];
    float4 e = reinterpret_cast<const float4*>(edge_rep)[i];
    float4 o;
    o.x = fmaf(c, e.x, fmaxf(0.f, fmaf(y.x, sc[h + 0], sh[h + 0])));
    o.y = fmaf(c, e.y, fmaxf(0.f, fmaf(y.y, sc[h + 1], sh[h + 1])));
    o.z = fmaf(c, e.z, fmaxf(0.f, fmaf(y.z, sc[h + 2], sh[h + 2])));
    o.w = fmaf(c, e.w, fmaxf(0.f, fmaf(y.w, sc[h + 3], sh[h + 3])));
    store_h4(Ah, (size_t)i * 4, o);
}

__global__ void edge_out_scatter(const float* __restrict__ Y, const float* __restrict__ Y2,
                                 const int* __restrict__ src, const int* __restrict__ dst,
                                 float* __restrict__ outE, float* __restrict__ S,
                                 int sO, const float* __restrict__ GO, const float* __restrict__ BO,
                                 int sS, const float* __restrict__ GS, const float* __restrict__ BS,
                                 float Rinv) {
    __shared__ float scO[128], shO[128], scS[128], shS[128];
    int t = threadIdx.x;
    if (t < 128) {
        float mean = g_stats[sO][0][t] * Rinv;
        float var  = g_stats[sO][1][t] * Rinv - mean * mean;
        float s    = GO[t] * rsqrtf(var + BN_EPS);
        scO[t] = s; shO[t] = fmaf(-mean, s, BO[t]);
        mean = g_stats[sS][0][t] * Rinv;
        var  = g_stats[sS][1][t] * Rinv - mean * mean;
        s    = GS[t] * rsqrtf(var + BN_EPS);
        scS[t] = s; shS[t] = fmaf(-mean, s, BS[t]);
    }
    __syncthreads();
    int i = blockIdx.x * 256 + threadIdx.x;
    if (i >= NE * 32) return;
    int e = i >> 5, q = i & 31;
    int h = q * 4;
    float4 y = reinterpret_cast<const float4*>(Y)[i];
    float4 o;
    o.x = fmaxf(0.f, fmaf(y.x, scO[h + 0], shO[h + 0]));
    o.y = fmaxf(0.f, fmaf(y.y, scO[h + 1], shO[h + 1]));
    o.z = fmaxf(0.f, fmaf(y.z, scO[h + 2], shO[h + 2]));
    o.w = fmaxf(0.f, fmaf(y.w, scO[h + 3], shO[h + 3]));
    reinterpret_cast<float4*>(outE)[i] = o;
    float4 y2 = reinterpret_cast<const float4*>(Y2)[i];
    float v0 = fmaxf(0.f, fmaf(y2.x, scS[h + 0], shS[h + 0]));
    float v1 = fmaxf(0.f, fmaf(y2.y, scS[h + 1], shS[h + 1]));
    float v2 = fmaxf(0.f, fmaf(y2.z, scS[h + 2], shS[h + 2]));
    float v3 = fmaxf(0.f, fmaf(y2.w, scS[h + 3], shS[h + 3]));
    int s = src[e], d = dst[e];
    red4(S + (size_t)s * HH + h, v0, v1, v2, v3);
    red4(S + (size_t)d * HH + h, v0, v1, v2, v3);
}

__global__ void apply_out(const float* __restrict__ Y, float* __restrict__ out, int nvec,
                          int slot, const float* __restrict__ G, const float* __restrict__ B,
                          float Rinv) {
    __shared__ float sc[128], sh[128];
    bn_prep128(sc, sh, slot, G, B, Rinv);
    int i = blockIdx.x * 256 + threadIdx.x;
    if (i >= nvec) return;
    int h = (i & 31) * 4;
    float4 y = reinterpret_cast<const float4*>(Y)[i];
    float4 o;
    o.x = fmaxf(0.f, fmaf(y.x, sc[h + 0], sh[h + 0]));
    o.y = fmaxf(0.f, fmaf(y.y, sc[h + 1], sh[h + 1]));
    o.z = fmaxf(0.f, fmaf(y.z, sc[h + 2], sh[h + 2]));
    o.w = fmaxf(0.f, fmaf(y.w, sc[h + 3], sh[h + 3]));
    reinterpret_cast<float4*>(out)[i] = o;
}

__global__ void make_node_in(const float* __restrict__ node_rep, const float* __restrict__ degree,
                             const float* __restrict__ S, const float* __restrict__ eps2,
                             __half* __restrict__ Ah) {
    int i = blockIdx.x * blockDim.x + threadIdx.x;
    if (i >= NN * 32) return;
    int n = i >> 5;
    float c = 1.f + eps2[0] - degree[n];
    float4 a = reinterpret_cast<const float4*>(node_rep)[i];
    float4 s = reinterpret_cast<const float4*>(S)[i];
    store_h4(Ah, (size_t)i * 4,
             make_float4(fmaf(c, a.x, s.x), fmaf(c, a.y, s.y),
                         fmaf(c, a.z, s.z), fmaf(c, a.w, s.w)));
}

// ---------------- host ----------------
extern "C" void kernel_launch(void* const* d_in, const int* in_sizes, int n_in,
                              void* d_out, int out_size) {
    const float* node_rep = (const float*)d_in[0];
    const float* edge_rep = (const float*)d_in[1];
    const float* degree   = (const float*)d_in[2];
    const int*   src      = (const int*)  d_in[3];
    const int*   dst      = (const int*)  d_in[4];
    const float* eps1     = (const float*)d_in[5];
    const float* eps2     = (const float*)d_in[6];
    const float* nW1 = (const float*)d_in[7],  *nG1 = (const float*)d_in[8],  *nB1 = (const float*)d_in[9];
    const float* nW2 = (const float*)d_in[10], *nG2 = (const float*)d_in[11], *nB2 = (const float*)d_in[12];
    const float* e0W1 = (const float*)d_in[13], *e0G1 = (const float*)d_in[14], *e0B1 = (const float*)d_in[15];
    const float* e0W2 = (const float*)d_in[16], *e0G2 = (const float*)d_in[17], *e0B2 = (const float*)d_in[18];
    const float* e1W1 = (const float*)d_in[19], *e1G1 = (const float*)d_in[20], *e1B1 = (const float*)d_in[21];
    const float* e1W2 = (const float*)d_in[22], *e1G2 = (const float*)d_in[23], *e1B2 = (const float*)d_in[24];
    const float* e2W1 = (const float*)d_in[25], *e2G1 = (const float*)d_in[26], *e2B1 = (const float*)d_in[27];
    const float* e2W2 = (const float*)d_in[28], *e2G2 = (const float*)d_in[29], *e2B2 = (const float*)d_in[30];

    float* out_node = (float*)d_out;
    float* out_edge = out_node + (size_t)NN * HH;

    cudaFuncSetAttribute(gemm_a16, cudaFuncAttributeMaxDynamicSharedMemorySize, GSMEM16);
    cudaFuncSetAttribute(gemm_a32, cudaFuncAttributeMaxDynamicSharedMemorySize, GSMEM32);

    float *S, *Hb, *Y, *Y2;
    __half *AH, *Wf;
    cudaGetSymbolAddress((void**)&S,  g_S);
    cudaGetSymbolAddress((void**)&Hb, g_Hb);
    cudaGetSymbolAddress((void**)&Y,  g_Y);
    cudaGetSymbolAddress((void**)&Y2, g_Y2);
    cudaGetSymbolAddress((void**)&AH, g_AH);
    cudaGetSymbolAddress((void**)&Wf, g_Wf);

    const int EV = NE * 32;
    const int NV = NN * 32;
    const float RinvE = 1.0f / (float)NE;
    const float RinvN = 1.0f / (float)NN;
    const unsigned gyE = (unsigned)cdivl(NE, 128);
    const unsigned gyN = (unsigned)cdivl(NN, 128);

    init_all<<<(unsigned)cdivl(INIT_TOTAL, 256), 256>>>(e0W1, e0W2, e1W1, e2W1,
                                                        e1W2, e2W2, nW1, nW2);
    scatter_edge<<<(unsigned)cdivl(EV, 256), 256>>>(edge_rep, src, dst, S);
    build_x0<<<(unsigned)cdivl(EV, 256), 256>>>(node_rep, S, src, dst, AH);

    gemm_a16<<<dim3(2, gyE), 256, GSMEM16>>>(AH, H2, Wf + OFF_E0W1, Hb, 512, NE, H2, 0);
    gemm_a32<<<dim3(1, gyE), 256, GSMEM32>>>(Hb, 512, Wf + OFF_E0W2,
                                             Y, 128, NE, H2, 0, 1, e0G1, e0B1, RinvE);
    make_edge_new<<<(unsigned)cdivl(EV, 256), 256>>>(Y, edge_rep, eps1, 1, e0G2, e0B2,
                                                     RinvE, AH);
    gemm_a16<<<dim3(4, gyE), 256, GSMEM16>>>(AH, HH, Wf + OFF_E1W1, Hb, 512, NE, HH, 2);
    gemm_a32<<<dim3(1, gyE), 256, GSMEM32>>>(Hb, 512, Wf + OFF_E1W2,
                                             Y, 128, NE, H2, 2, 4, e1G1, e1B1, RinvE);
    gemm_a32<<<dim3(1, gyE), 256, GSMEM32>>>(Hb + 256, 512, Wf + OFF_E2W2,
                                             Y2, 128, NE, H2, 3, 5, e2G1, e2B1, RinvE);
    zero_f4<<<(unsigned)cdivl((long)NN * HH / 4, 256), 256>>>((float4*)S, NN * HH / 4);
    edge_out_scatter<<<(unsigned)cdivl(EV, 256), 256>>>(Y, Y2, src, dst, out_edge, S,
                                                        4, e1G2, e1B2, 5, e2G2, e2B2, RinvE);
    make_node_in<<<(unsigned)cdivl(NV, 256), 256>>>(node_rep, degree, S, eps2, AH);
    gemm_a16<<<dim3(2, gyN), 256, GSMEM16>>>(AH, HH, Wf + OFF_NW1, Hb, 512, NN, HH, 6);
    gemm_a32<<<dim3(1, gyN), 256, GSMEM32>>>(Hb, 512, Wf + OFF_NW2,
                                             Y, 128, NN, H2, 6, 7, nG1, nB1, RinvN);
    apply_out<<<(unsigned)cdivl(NV, 256), 256>>>(Y, out_node, NV, 7, nG2, nB2, RinvN);
}

// round 16
// speedup vs baseline: 1.4089x; 1.0500x over previous
#include <cuda_runtime.h>
#include <cuda_fp16.h>
#include <cstdint>
#include <cstddef>

#define NN 50000
#define NE 400000
#define HH 128
#define H2 256
#define BN_EPS 1e-5f

// ---------------- scratch ----------------
static __device__ float g_S [(size_t)NN * HH];
static __device__ __half g_Hb[(size_t)NE * 512];    // hidden layer, fp16
static __device__ float g_Y [(size_t)NE * HH];
static __device__ float g_Y2[(size_t)NE * HH];
static __device__ float g_stats[8][2][256];
static __device__ __half g_AH[(size_t)NE * H2];
static __device__ __half g_Wf[294912];

#define OFF_E0W1 0
#define OFF_E0W2 65536
#define OFF_E1W1 98304
#define OFF_E2W1 131072
#define OFF_E1W2 163840
#define OFF_E2W2 196608
#define OFF_NW1  229376
#define OFF_NW2  262144

static inline long cdivl(long a, long b) { return (a + b - 1) / b; }

__device__ __forceinline__ uint32_t smem_to_u32(const void* p) {
    uint32_t a;
    asm("{ .reg .u64 t; cvta.to.shared.u64 t, %1; cvt.u32.u64 %0, t; }" : "=r"(a) : "l"(p));
    return a;
}

#define LDMX4(r, addr) \
    asm volatile("ldmatrix.sync.aligned.m8n8.x4.shared.b16 {%0,%1,%2,%3}, [%4];" \
        : "=r"((r)[0]), "=r"((r)[1]), "=r"((r)[2]), "=r"((r)[3]) : "r"(addr))

#define MMA16816(d, a, b0, b1) \
    asm volatile("mma.sync.aligned.m16n8k16.row.col.f32.f16.f16.f32 " \
        "{%0,%1,%2,%3},{%4,%5,%6,%7},{%8,%9},{%0,%1,%2,%3};" \
        : "+f"((d)[0]), "+f"((d)[1]), "+f"((d)[2]), "+f"((d)[3]) \
        : "r"((a)[0]), "r"((a)[1]), "r"((a)[2]), "r"((a)[3]), "r"(b0), "r"(b1))

__device__ __forceinline__ void cp16(uint32_t dst, const void* src) {
    asm volatile("cp.async.cg.shared.global [%0], [%1], 16;" :: "r"(dst), "l"(src));
}
#define CP_COMMIT() asm volatile("cp.async.commit_group;" ::: "memory")
#define CP_WAIT(n)  asm volatile("cp.async.wait_group %0;" :: "n"(n) : "memory")

__device__ __forceinline__ void red4(float* p, float a, float b, float c, float d) {
    asm volatile("red.global.add.v4.f32 [%0], {%1,%2,%3,%4};"
                 :: "l"(p), "f"(a), "f"(b), "f"(c), "f"(d) : "memory");
}

__device__ __forceinline__ uint32_t sw64(uint32_t off)  { return off ^ ((off >> 3) & 0x30); }
__device__ __forceinline__ uint32_t sw128(uint32_t off) { return off ^ ((off >> 3) & 0x70); }

__device__ __forceinline__ void store_h4(__half* dst, size_t idx, float4 v) {
    __half2 xy = __floats2half2_rn(v.x, v.y);
    __half2 zw = __floats2half2_rn(v.z, v.w);
    *reinterpret_cast<uint2*>(dst + idx) =
        make_uint2(*reinterpret_cast<uint32_t*>(&xy), *reinterpret_cast<uint32_t*>(&zw));
}

// ---------------- init ----------------
#define NS4 ((NN * HH) / 4)
#define R_STATS 1024
#define R_W 294912
#define INIT_TOTAL (NS4 + R_STATS + R_W)

__global__ void init_all(const float* w0, const float* w1, const float* w2, const float* w3,
                         const float* w4, const float* w5, const float* w6, const float* w7) {
    int gid = blockIdx.x * blockDim.x + threadIdx.x;
    if (gid < NS4) {
        reinterpret_cast<float4*>(g_S)[gid] = make_float4(0.f, 0.f, 0.f, 0.f);
        return;
    }
    gid -= NS4;
    if (gid < R_STATS) {
        reinterpret_cast<float4*>(g_stats)[gid] = make_float4(0.f, 0.f, 0.f, 0.f);
        return;
    }
    gid -= R_STATS;
    if (gid >= R_W) return;
    const float* ws[8] = {w0, w1, w2, w3, w4, w5, w6, w7};
    const int segSize[8] = {65536, 32768, 32768, 32768, 32768, 32768, 32768, 32768};
    const int segK[8]    = {256, 256, 128, 128, 256, 256, 128, 256};
    int seg = 0, base = 0, idx = gid;
#pragma unroll
    for (int s = 0; s < 8; s++) {
        if (idx < segSize[s]) { seg = s; break; }
        idx -= segSize[s];
        base += segSize[s];
    }
    int Kw = segK[seg];
    int Nw = segSize[seg] / Kw;
    int k = idx / Nw, n = idx % Nw;
    g_Wf[base + n * Kw + k] = __float2half_rn(ws[seg][idx]);
}

// ---------------- graph kernels ----------------
__global__ void zero_f4(float4* p, int n4) {
    int i = blockIdx.x * blockDim.x + threadIdx.x;
    if (i < n4) p[i] = make_float4(0.f, 0.f, 0.f, 0.f);
}

__global__ void scatter_edge(const float* __restrict__ edge_rep,
                             const int* __restrict__ src, const int* __restrict__ dst,
                             float* __restrict__ S) {
    int tid = blockIdx.x * blockDim.x + threadIdx.x;
    if (tid >= NE * 32) return;
    int e = tid >> 5, q = tid & 31;
    float4 v = reinterpret_cast<const float4*>(edge_rep)[(size_t)e * 32 + q];
    int s = src[e], d = dst[e];
    red4(S + (size_t)s * HH + q * 4, v.x, v.y, v.z, v.w);
    red4(S + (size_t)d * HH + q * 4, v.x, v.y, v.z, v.w);
}

__global__ void build_x0(const float* __restrict__ node_rep, const float* __restrict__ S,
                         const int* __restrict__ src, const int* __restrict__ dst,
                         __half* __restrict__ Ah) {
    int tid = blockIdx.x * blockDim.x + threadIdx.x;
    if (tid >= NE * 32) return;
    int e = tid >> 5, q = tid & 31;
    int s = src[e], d = dst[e];
    const float4* nr4 = reinterpret_cast<const float4*>(node_rep);
    const float4* S4  = reinterpret_cast<const float4*>(S);
    float4 a0 = nr4[(size_t)s * 32 + q], a1 = nr4[(size_t)d * 32 + q];
    float4 b0 = S4 [(size_t)s * 32 + q], b1 = S4 [(size_t)d * 32 + q];
    store_h4(Ah, (size_t)e * 256 + q * 4,
             make_float4(a0.x + a1.x, a0.y + a1.y, a0.z + a1.z, a0.w + a1.w));
    store_h4(Ah, (size_t)e * 256 + 128 + q * 4,
             make_float4(b0.x + b1.x, b0.y + b1.y, b0.z + b1.z, b0.w + b1.w));
}

// ---------------- a16 core: BK=64, SW128 rows, 8 warps (4m x 2n), tile 32x64 -------------
#define A64_A 0
#define A64_B 16384
#define STG64 32768
#define GSMEM16 (3 * STG64)

#define MMA_CHUNK64(uStage, acc, rAoff, rBoff, kb)                                 \
    do {                                                                           \
        uint32_t ah[2][4], bb[4][4];                                               \
        _Pragma("unroll")                                                          \
        for (int mt = 0; mt < 2; mt++) {                                           \
            uint32_t sw = sw128(rAoff[mt] + (kb));                                 \
            LDMX4(ah[mt], (uStage) + A64_A + sw);                                  \
        }                                                                          \
        _Pragma("unroll")                                                          \
        for (int t = 0; t < 4; t++) {                                              \
            uint32_t sw = sw128(rBoff[t] + (kb));                                  \
            LDMX4(bb[t], (uStage) + A64_B + sw);                                   \
        }                                                                          \
        _Pragma("unroll")                                                          \
        for (int mt = 0; mt < 2; mt++)                                             \
            _Pragma("unroll")                                                      \
            for (int t = 0; t < 4; t++) {                                          \
                MMA16816(acc[mt][t * 2 + 0], ah[mt], bb[t][0], bb[t][2]);          \
                MMA16816(acc[mt][t * 2 + 1], ah[mt], bb[t][1], bb[t][3]);          \
            }                                                                      \
    } while (0)

// C output is fp16 (Hb)
__global__ void __launch_bounds__(256, 2)
gemm_a16(const __half* __restrict__ Ah, int lda, const __half* __restrict__ Bw,
         __half* __restrict__ C, int ldc, int R, int K, int outSlotBase) {
    extern __shared__ __align__(128) char sm[];
    __shared__ float s_csum[128], s_css[128];
    const uint32_t uS = smem_to_u32(sm);

    const int tid  = threadIdx.x;
    const int wid  = tid >> 5;
    const int lane = tid & 31;
    const int m0     = blockIdx.y * 128;
    const int bnBase = blockIdx.x * 128;
    const int wm = (wid & 3) * 32;
    const int wn = (wid >> 2) * 64;

    if (tid < 128) { s_csum[tid] = 0.f; s_css[tid] = 0.f; }
    __syncthreads();

    float acc[2][8][4];
#pragma unroll
    for (int mt = 0; mt < 2; mt++)
#pragma unroll
        for (int nt = 0; nt < 8; nt++)
#pragma unroll
            for (int j = 0; j < 4; j++) acc[mt][nt][j] = 0.f;

    const int nchunks = K >> 6;

    uint32_t rAoff[2], rBoff[4];
#pragma unroll
    for (int mt = 0; mt < 2; mt++) rAoff[mt] = (wm + mt * 16 + (lane & 15)) * 128;
#pragma unroll
    for (int t = 0; t < 4; t++)    rBoff[t]  = (wn + t * 16 + (lane & 15)) * 128;
    const uint32_t kb0 = (lane >> 4) << 4;

    uint32_t swp[4];
    int prow[4], pf[4];
#pragma unroll
    for (int j = 0; j < 4; j++) {
        int p = tid + j * 256;
        prow[j] = p >> 3; pf[j] = p & 7;
        swp[j] = sw128(prow[j] * 128 + pf[j] * 16);
    }

    auto issue = [&](int kc) {
        uint32_t uDst = uS + (kc % 3) * STG64;
#pragma unroll
        for (int j = 0; j < 4; j++) {
            cp16(uDst + A64_A + swp[j], Ah + (size_t)(m0 + prow[j]) * lda + kc * 64 + pf[j] * 8);
            cp16(uDst + A64_B + swp[j], Bw + (size_t)(bnBase + prow[j]) * K + kc * 64 + pf[j] * 8);
        }
        CP_COMMIT();
    };

    issue(0);
    if (nchunks > 1) issue(1);

    for (int kc = 0; kc < nchunks; kc++) {
        if (kc + 1 < nchunks) { CP_WAIT(1); } else { CP_WAIT(0); }
        __syncthreads();
        if (kc + 2 < nchunks) issue(kc + 2);
        const uint32_t uStage = uS + (kc % 3) * STG64;
        MMA_CHUNK64(uStage, acc, rAoff, rBoff, kb0);
        MMA_CHUNK64(uStage, acc, rAoff, rBoff, kb0 + 32);
        MMA_CHUNK64(uStage, acc, rAoff, rBoff, kb0 + 64);
        MMA_CHUNK64(uStage, acc, rAoff, rBoff, kb0 + 96);
    }

#pragma unroll
    for (int mt = 0; mt < 2; mt++) {
        const int row0 = m0 + wm + mt * 16 + (lane >> 2);
#pragma unroll
        for (int nt = 0; nt < 8; nt++) {
            float c0 = acc[mt][nt][0], c1 = acc[mt][nt][1];
            float c2 = acc[mt][nt][2], c3 = acc[mt][nt][3];
            const int cl = wn + nt * 8 + (lane & 3) * 2;
            if (row0 < R) {
                __half2 h = __floats2half2_rn(c0, c1);
                *reinterpret_cast<uint32_t*>(C + (size_t)row0 * ldc + bnBase + cl) =
                    *reinterpret_cast<uint32_t*>(&h);
            } else { c0 = 0.f; c1 = 0.f; }
            if (row0 + 8 < R) {
                __half2 h = __floats2half2_rn(c2, c3);
                *reinterpret_cast<uint32_t*>(C + (size_t)(row0 + 8) * ldc + bnBase + cl) =
                    *reinterpret_cast<uint32_t*>(&h);
            } else { c2 = 0.f; c3 = 0.f; }
            float se = c0 + c2, so = c1 + c3;
            float qe = fmaf(c0, c0, c2 * c2), qo = fmaf(c1, c1, c3 * c3);
#pragma unroll
            for (int off = 16; off >= 4; off >>= 1) {
                se += __shfl_down_sync(0xffffffffu, se, off);
                so += __shfl_down_sync(0xffffffffu, so, off);
                qe += __shfl_down_sync(0xffffffffu, qe, off);
                qo += __shfl_down_sync(0xffffffffu, qo, off);
            }
            if (lane < 4) {
                int c = wn + nt * 8 + lane * 2;
                atomicAdd(&s_csum[c], se); atomicAdd(&s_csum[c + 1], so);
                atomicAdd(&s_css [c], qe); atomicAdd(&s_css [c + 1], qo);
            }
        }
    }
    __syncthreads();
    if (tid < 256) {
        int c = tid & 127;
        int colg = bnBase + c;
        int slot = outSlotBase + (colg >> 8);
        int colIn = colg & 255;
        if (tid < 128) atomicAdd(&g_stats[slot][0][colIn], s_csum[c]);
        else           atomicAdd(&g_stats[slot][1][colIn], s_css[c]);
    }
}

// ------- GEMM a32: fp16 Hb in + fused BN+ReLU -> fp16 plane, BK=32, 2 stages -------
#define S16_A 0
#define S16_B 8192
#define STG16 16384
#define GSMEM32 (2 * STG16)

#define MMA_CHUNK1(uStage, acc, rAoff, rBoff, kb)                                  \
    do {                                                                           \
        uint32_t ah[2][4], bb[4][4];                                               \
        _Pragma("unroll")                                                          \
        for (int mt = 0; mt < 2; mt++) {                                           \
            uint32_t sw = sw64(rAoff[mt] + (kb));                                  \
            LDMX4(ah[mt], (uStage) + S16_A + sw);                                  \
        }                                                                          \
        _Pragma("unroll")                                                          \
        for (int t = 0; t < 4; t++) {                                              \
            uint32_t sw = sw64(rBoff[t] + (kb));                                   \
            LDMX4(bb[t], (uStage) + S16_B + sw);                                   \
        }                                                                          \
        _Pragma("unroll")                                                          \
        for (int mt = 0; mt < 2; mt++)                                             \
            _Pragma("unroll")                                                      \
            for (int t = 0; t < 4; t++) {                                          \
                MMA16816(acc[mt][t * 2 + 0], ah[mt], bb[t][0], bb[t][2]);          \
                MMA16816(acc[mt][t * 2 + 1], ah[mt], bb[t][1], bb[t][3]);          \
            }                                                                      \
    } while (0)

__global__ void __launch_bounds__(256, 2)
gemm_a32(const __half* __restrict__ A, int lda, const __half* __restrict__ Bw,
         float* __restrict__ C, int ldc, int R, int K,
         int inSlot, int outSlotBase,
         const float* __restrict__ Gp, const float* __restrict__ Bp, float Rinv) {
    extern __shared__ __align__(128) char sm[];
    __shared__ float s_scale[256], s_shift[256];
    __shared__ float s_csum[128], s_css[128];
    const uint32_t uS = smem_to_u32(sm);

    const int tid  = threadIdx.x;
    const int wid  = tid >> 5;
    const int lane = tid & 31;
    const int m0     = blockIdx.y * 128;
    const int bnBase = blockIdx.x * 128;
    const int wm = (wid & 3) * 32;
    const int wn = (wid >> 2) * 64;

    for (int c = tid; c < K; c += 256) {
        float mean = g_stats[inSlot][0][c] * Rinv;
        float var  = g_stats[inSlot][1][c] * Rinv - mean * mean;
        float s    = Gp[c] * rsqrtf(var + BN_EPS);
        s_scale[c] = s;
        s_shift[c] = fmaf(-mean, s, Bp[c]);
    }
    if (tid < 128) { s_csum[tid] = 0.f; s_css[tid] = 0.f; }
    __syncthreads();

    float acc[2][8][4];
#pragma unroll
    for (int mt = 0; mt < 2; mt++)
#pragma unroll
        for (int nt = 0; nt < 8; nt++)
#pragma unroll
            for (int j = 0; j < 4; j++) acc[mt][nt][j] = 0.f;

    const int nchunks = K >> 5;
    const int arow_i = tid >> 1;
    const int acb    = (tid & 1) * 16;
    const int agr    = m0 + arow_i;
    uint4 areg[2];           // 16 fp16 values

    uint32_t rAoff[2], rBoff[4];
#pragma unroll
    for (int mt = 0; mt < 2; mt++) rAoff[mt] = (wm + mt * 16 + (lane & 15)) * 64;
#pragma unroll
    for (int t = 0; t < 4; t++)    rBoff[t]  = (wn + t * 16 + (lane & 15)) * 64;
    const uint32_t kb0 = (lane >> 4) << 4;

    {
#pragma unroll
        for (int j = 0; j < 2; j++) {
            int p = tid + j * 256;
            int n = p >> 2, f = p & 3;
            uint32_t sw = sw64(n * 64 + f * 16);
            cp16(uS + S16_B + sw, Bw + (size_t)(bnBase + n) * K + f * 8);
        }
        CP_COMMIT();
        const uint4* ap = reinterpret_cast<const uint4*>(A + (size_t)agr * lda + acb);
#pragma unroll
        for (int j = 0; j < 2; j++)
            areg[j] = (agr < R) ? ap[j] : make_uint4(0u, 0u, 0u, 0u);
    }

    for (int kc = 0; kc < nchunks; kc++) {
        const int s = kc & 1;
        const uint32_t uStage = uS + s * STG16;
        {
            uint32_t h2v[8] = {areg[0].x, areg[0].y, areg[0].z, areg[0].w,
                               areg[1].x, areg[1].y, areg[1].z, areg[1].w};
#pragma unroll
            for (int f = 0; f < 4; f++) {
                __half2 p0 = *reinterpret_cast<__half2*>(&h2v[2 * f]);
                __half2 p1 = *reinterpret_cast<__half2*>(&h2v[2 * f + 1]);
                float2 f0 = __half22float2(p0), f1 = __half22float2(p1);
                if (agr < R) {
                    int k = kc * 32 + acb + f * 4;
                    f0.x = fmaxf(0.f, fmaf(f0.x, s_scale[k + 0], s_shift[k + 0]));
                    f0.y = fmaxf(0.f, fmaf(f0.y, s_scale[k + 1], s_shift[k + 1]));
                    f1.x = fmaxf(0.f, fmaf(f1.x, s_scale[k + 2], s_shift[k + 2]));
                    f1.y = fmaxf(0.f, fmaf(f1.y, s_scale[k + 3], s_shift[k + 3]));
                }
                __half2 o0 = __floats2half2_rn(f0.x, f0.y);
                __half2 o1 = __floats2half2_rn(f1.x, f1.y);
                uint32_t sw = sw64(arow_i * 64 + (acb + f * 4) * 2);
                *reinterpret_cast<uint2*>(sm + s * STG16 + S16_A + sw) =
                    make_uint2(*reinterpret_cast<uint32_t*>(&o0),
                               *reinterpret_cast<uint32_t*>(&o1));
            }
        }
        if (kc + 1 < nchunks) {
            const uint4* ap = reinterpret_cast<const uint4*>(A + (size_t)agr * lda +
                                                             (kc + 1) * 32 + acb);
#pragma unroll
            for (int j = 0; j < 2; j++)
                areg[j] = (agr < R) ? ap[j] : make_uint4(0u, 0u, 0u, 0u);
        }
        CP_WAIT(0);
        __syncthreads();
        if (kc + 1 < nchunks) {
            const uint32_t uN = uS + (s ^ 1) * STG16;
#pragma unroll
            for (int j = 0; j < 2; j++) {
                int p = tid + j * 256;
                int n = p >> 2, f = p & 3;
                uint32_t sw = sw64(n * 64 + f * 16);
                cp16(uN + S16_B + sw, Bw + (size_t)(bnBase + n) * K + (kc + 1) * 32 + f * 8);
            }
            CP_COMMIT();
        }
        MMA_CHUNK1(uStage, acc, rAoff, rBoff, kb0);
        MMA_CHUNK1(uStage, acc, rAoff, rBoff, kb0 + 32);
    }

#pragma unroll
    for (int mt = 0; mt < 2; mt++) {
        const int row0 = m0 + wm + mt * 16 + (lane >> 2);
#pragma unroll
        for (int nt = 0; nt < 8; nt++) {
            float c0 = acc[mt][nt][0], c1 = acc[mt][nt][1];
            float c2 = acc[mt][nt][2], c3 = acc[mt][nt][3];
            const int cl = wn + nt * 8 + (lane & 3) * 2;
            if (row0 < R)
                *reinterpret_cast<float2*>(C + (size_t)row0 * ldc + bnBase + cl) =
                    make_float2(c0, c1);
            if (row0 + 8 < R)
                *reinterpret_cast<float2*>(C + (size_t)(row0 + 8) * ldc + bnBase + cl) =
                    make_float2(c2, c3);
            float se = c0 + c2, so = c1 + c3;
            float qe = fmaf(c0, c0, c2 * c2), qo = fmaf(c1, c1, c3 * c3);
#pragma unroll
            for (int off = 16; off >= 4; off >>= 1) {
                se += __shfl_down_sync(0xffffffffu, se, off);
                so += __shfl_down_sync(0xffffffffu, so, off);
                qe += __shfl_down_sync(0xffffffffu, qe, off);
                qo += __shfl_down_sync(0xffffffffu, qo, off);
            }
            if (lane < 4) {
                int c = wn + nt * 8 + lane * 2;
                atomicAdd(&s_csum[c], se); atomicAdd(&s_csum[c + 1], so);
                atomicAdd(&s_css [c], qe); atomicAdd(&s_css [c + 1], qo);
            }
        }
    }
    __syncthreads();
    if (tid < 256) {
        int c = tid & 127;
        int colg = bnBase + c;
        int slot = outSlotBase + (colg >> 8);
        int colIn = colg & 255;
        if (tid < 128) atomicAdd(&g_stats[slot][0][colIn], s_csum[c]);
        else           atomicAdd(&g_stats[slot][1][colIn], s_css[c]);
    }
}

// ---------------- consumers ----------------
__device__ __forceinline__ void bn_prep128(float* sc, float* sh, int slot,
                                           const float* G, const float* B, float Rinv) {
    int t = threadIdx.x;
    if (t < 128) {
        float mean = g_stats[slot][0][t] * Rinv;
        float var  = g_stats[slot][1][t] * Rinv - mean * mean;
        float s    = G[t] * rsqrtf(var + BN_EPS);
        sc[t] = s;
        sh[t] = fmaf(-mean, s, B[t]);
    }
    __syncthreads();
}

__global__ void make_edge_new(const float* __restrict__ Y, const float* __restrict__ edge_rep,
                              const float* __restrict__ eps1, int slot,
                              const float* __restrict__ G, const float* __restrict__ B,
                              float Rinv, __half* __restrict__ Ah) {
    __shared__ float sc[128], sh[128];
    bn_prep128(sc, sh, slot, G, B, Rinv);
    int i = blockIdx.x * 256 + threadIdx.x;
    if (i >= NE * 32) return;
    int h = (i & 31) * 4;
    float c = 1.f + eps1[0];
    float4 y = reinterpret_cast<const float4*>(Y)[i];
    float4 e = reinterpret_cast<const float4*>(edge_rep)[i];
    float4 o;
    o.x = fmaf(c, e.x, fmaxf(0.f, fmaf(y.x, sc[h + 0], sh[h + 0])));
    o.y = fmaf(c, e.y, fmaxf(0.f, fmaf(y.y, sc[h + 1], sh[h + 1])));
    o.z = fmaf(c, e.z, fmaxf(0.f, fmaf(y.z, sc[h + 2], sh[h + 2])));
    o.w = fmaf(c, e.w, fmaxf(0.f, fmaf(y.w, sc[h + 3], sh[h + 3])));
    store_h4(Ah, (size_t)i * 4, o);
}

__global__ void edge_out_scatter(const float* __restrict__ Y, const float* __restrict__ Y2,
                                 const int* __restrict__ src, const int* __restrict__ dst,
                                 float* __restrict__ outE, float* __restrict__ S,
                                 int sO, const float* __restrict__ GO, const float* __restrict__ BO,
                                 int sS, const float* __restrict__ GS, const float* __restrict__ BS,
                                 float Rinv) {
    __shared__ float scO[128], shO[128], scS[128], shS[128];
    int t = threadIdx.x;
    if (t < 128) {
        float mean = g_stats[sO][0][t] * Rinv;
        float var  = g_stats[sO][1][t] * Rinv - mean * mean;
        float s    = GO[t] * rsqrtf(var + BN_EPS);
        scO[t] = s; shO[t] = fmaf(-mean, s, BO[t]);
        mean = g_stats[sS][0][t] * Rinv;
        var  = g_stats[sS][1][t] * Rinv - mean * mean;
        s    = GS[t] * rsqrtf(var + BN_EPS);
        scS[t] = s; shS[t] = fmaf(-mean, s, BS[t]);
    }
    __syncthreads();
    int i = blockIdx.x * 256 + threadIdx.x;
    if (i >= NE * 32) return;
    int e = i >> 5, q = i & 31;
    int h = q * 4;
    float4 y = reinterpret_cast<const float4*>(Y)[i];
    float4 o;
    o.x = fmaxf(0.f, fmaf(y.x, scO[h + 0], shO[h + 0]));
    o.y = fmaxf(0.f, fmaf(y.y, scO[h + 1], shO[h + 1]));
    o.z = fmaxf(0.f, fmaf(y.z, scO[h + 2], shO[h + 2]));
    o.w = fmaxf(0.f, fmaf(y.w, scO[h + 3], shO[h + 3]));
    reinterpret_cast<float4*>(outE)[i] = o;
    float4 y2 = reinterpret_cast<const float4*>(Y2)[i];
    float v0 = fmaxf(0.f, fmaf(y2.x, scS[h + 0], shS[h + 0]));
    float v1 = fmaxf(0.f, fmaf(y2.y, scS[h + 1], shS[h + 1]));
    float v2 = fmaxf(0.f, fmaf(y2.z, scS[h + 2], shS[h + 2]));
    float v3 = fmaxf(0.f, fmaf(y2.w, scS[h + 3], shS[h + 3]));
    int s = src[e], d = dst[e];
    red4(S + (size_t)s * HH + h, v0, v1, v2, v3);
    red4(S + (size_t)d * HH + h, v0, v1, v2, v3);
}

__global__ void apply_out(const float* __restrict__ Y, float* __restrict__ out, int nvec,
                          int slot, const float* __restrict__ G, const float* __restrict__ B,
                          float Rinv) {
    __shared__ float sc[128], sh[128];
    bn_prep128(sc, sh, slot, G, B, Rinv);
    int i = blockIdx.x * 256 + threadIdx.x;
    if (i >= nvec) return;
    int h = (i & 31) * 4;
    float4 y = reinterpret_cast<const float4*>(Y)[i];
    float4 o;
    o.x = fmaxf(0.f, fmaf(y.x, sc[h + 0], sh[h + 0]));
    o.y = fmaxf(0.f, fmaf(y.y, sc[h + 1], sh[h + 1]));
    o.z = fmaxf(0.f, fmaf(y.z, sc[h + 2], sh[h + 2]));
    o.w = fmaxf(0.f, fmaf(y.w, sc[h + 3], sh[h + 3]));
    reinterpret_cast<float4*>(out)[i] = o;
}

__global__ void make_node_in(const float* __restrict__ node_rep, const float* __restrict__ degree,
                             const float* __restrict__ S, const float* __restrict__ eps2,
                             __half* __restrict__ Ah) {
    int i = blockIdx.x * blockDim.x + threadIdx.x;
    if (i >= NN * 32) return;
    int n = i >> 5;
    float c = 1.f + eps2[0] - degree[n];
    float4 a = reinterpret_cast<const float4*>(node_rep)[i];
    float4 s = reinterpret_cast<const float4*>(S)[i];
    store_h4(Ah, (size_t)i * 4,
             make_float4(fmaf(c, a.x, s.x), fmaf(c, a.y, s.y),
                         fmaf(c, a.z, s.z), fmaf(c, a.w, s.w)));
}

// ---------------- host ----------------
extern "C" void kernel_launch(void* const* d_in, const int* in_sizes, int n_in,
                              void* d_out, int out_size) {
    const float* node_rep = (const float*)d_in[0];
    const float* edge_rep = (const float*)d_in[1];
    const float* degree   = (const float*)d_in[2];
    const int*   src      = (const int*)  d_in[3];
    const int*   dst      = (const int*)  d_in[4];
    const float* eps1     = (const float*)d_in[5];
    const float* eps2     = (const float*)d_in[6];
    const float* nW1 = (const float*)d_in[7],  *nG1 = (const float*)d_in[8],  *nB1 = (const float*)d_in[9];
    const float* nW2 = (const float*)d_in[10], *nG2 = (const float*)d_in[11], *nB2 = (const float*)d_in[12];
    const float* e0W1 = (const float*)d_in[13], *e0G1 = (const float*)d_in[14], *e0B1 = (const float*)d_in[15];
    const float* e0W2 = (const float*)d_in[16], *e0G2 = (const float*)d_in[17], *e0B2 = (const float*)d_in[18];
    const float* e1W1 = (const float*)d_in[19], *e1G1 = (const float*)d_in[20], *e1B1 = (const float*)d_in[21];
    const float* e1W2 = (const float*)d_in[22], *e1G2 = (const float*)d_in[23], *e1B2 = (const float*)d_in[24];
    const float* e2W1 = (const float*)d_in[25], *e2G1 = (const float*)d_in[26], *e2B1 = (const float*)d_in[27];
    const float* e2W2 = (const float*)d_in[28], *e2G2 = (const float*)d_in[29], *e2B2 = (const float*)d_in[30];

    float* out_node = (float*)d_out;
    float* out_edge = out_node + (size_t)NN * HH;

    cudaFuncSetAttribute(gemm_a16, cudaFuncAttributeMaxDynamicSharedMemorySize, GSMEM16);
    cudaFuncSetAttribute(gemm_a32, cudaFuncAttributeMaxDynamicSharedMemorySize, GSMEM32);

    float *S, *Y, *Y2;
    __half *Hb, *AH, *Wf;
    cudaGetSymbolAddress((void**)&S,  g_S);
    cudaGetSymbolAddress((void**)&Hb, g_Hb);
    cudaGetSymbolAddress((void**)&Y,  g_Y);
    cudaGetSymbolAddress((void**)&Y2, g_Y2);
    cudaGetSymbolAddress((void**)&AH, g_AH);
    cudaGetSymbolAddress((void**)&Wf, g_Wf);

    const int EV = NE * 32;
    const int NV = NN * 32;
    const float RinvE = 1.0f / (float)NE;
    const float RinvN = 1.0f / (float)NN;
    const unsigned gyE = (unsigned)cdivl(NE, 128);
    const unsigned gyN = (unsigned)cdivl(NN, 128);

    init_all<<<(unsigned)cdivl(INIT_TOTAL, 256), 256>>>(e0W1, e0W2, e1W1, e2W1,
                                                        e1W2, e2W2, nW1, nW2);
    scatter_edge<<<(unsigned)cdivl(EV, 256), 256>>>(edge_rep, src, dst, S);
    build_x0<<<(unsigned)cdivl(EV, 256), 256>>>(node_rep, S, src, dst, AH);

    gemm_a16<<<dim3(2, gyE), 256, GSMEM16>>>(AH, H2, Wf + OFF_E0W1, Hb, 512, NE, H2, 0);
    gemm_a32<<<dim3(1, gyE), 256, GSMEM32>>>(Hb, 512, Wf + OFF_E0W2,
                                             Y, 128, NE, H2, 0, 1, e0G1, e0B1, RinvE);
    make_edge_new<<<(unsigned)cdivl(EV, 256), 256>>>(Y, edge_rep, eps1, 1, e0G2, e0B2,
                                                     RinvE, AH);
    gemm_a16<<<dim3(4, gyE), 256, GSMEM16>>>(AH, HH, Wf + OFF_E1W1, Hb, 512, NE, HH, 2);
    gemm_a32<<<dim3(1, gyE), 256, GSMEM32>>>(Hb, 512, Wf + OFF_E1W2,
                                             Y, 128, NE, H2, 2, 4, e1G1, e1B1, RinvE);
    gemm_a32<<<dim3(1, gyE), 256, GSMEM32>>>(Hb + 256, 512, Wf + OFF_E2W2,
                                             Y2, 128, NE, H2, 3, 5, e2G1, e2B1, RinvE);
    zero_f4<<<(unsigned)cdivl((long)NN * HH / 4, 256), 256>>>((float4*)S, NN * HH / 4);
    edge_out_scatter<<<(unsigned)cdivl(EV, 256), 256>>>(Y, Y2, src, dst, out_edge, S,
                                                        4, e1G2, e1B2, 5, e2G2, e2B2, RinvE);
    make_node_in<<<(unsigned)cdivl(NV, 256), 256>>>(node_rep, degree, S, eps2, AH);
    gemm_a16<<<dim3(2, gyN), 256, GSMEM16>>>(AH, HH, Wf + OFF_NW1, Hb, 512, NN, HH, 6);
    gemm_a32<<<dim3(1, gyN), 256, GSMEM32>>>(Hb, 512, Wf + OFF_NW2,
                                             Y, 128, NN, H2, 6, 7, nG1, nB1, RinvN);
    apply_out<<<(unsigned)cdivl(NV, 256), 256>>>(Y, out_node, NV, 7, nG2, nB2, RinvN);
}